// round 2
// baseline (speedup 1.0000x reference)
#include <cuda_runtime.h>
#include <math.h>
#include <stdint.h>

#define SEQ   512
#define BATCH 64
#define DIN   1024
#define DLAT  1024
#define DCAT  2048
#define NGATE 4096   // 4 * DLAT

// Scratch (allocation-free rule: __device__ globals)
__device__ float g_gx[(size_t)SEQ * BATCH * NGATE];  // precomputed x-side gates (+bias)
__device__ float g_h0[BATCH * DLAT];                 // zero h_{-1}
__device__ float g_c [BATCH * DLAT];                 // cell state (block-exclusive j ranges)

// ---------- packed f32x2 helpers (Blackwell: 2x fp32 FMA rate) ----------
__device__ __forceinline__ unsigned long long pack2(float lo, float hi) {
    unsigned long long r;
    asm("mov.b64 %0, {%1, %2};" : "=l"(r) : "f"(lo), "f"(hi));
    return r;
}
__device__ __forceinline__ void unpack2(unsigned long long v, float& lo, float& hi) {
    asm("mov.b64 {%0, %1}, %2;" : "=f"(lo), "=f"(hi) : "l"(v));
}
__device__ __forceinline__ unsigned long long fma2(unsigned long long a,
                                                   unsigned long long b,
                                                   unsigned long long c) {
    unsigned long long d;
    asm("fma.rn.f32x2 %0, %1, %2, %3;" : "=l"(d) : "l"(a), "l"(b), "l"(c));
    return d;
}

__device__ __forceinline__ float sigmoidf_(float x) {
    return 1.0f / (1.0f + __expf(-x));
}

// ---------------------------------------------------------------
// init: zero h_{-1} and c (must run every kernel_launch call)
// ---------------------------------------------------------------
__global__ void init_state() {
    int i = blockIdx.x * blockDim.x + threadIdx.x;
    if (i < BATCH * DLAT) { g_h0[i] = 0.0f; g_c[i] = 0.0f; }
}

// ---------------------------------------------------------------
// Phase A: gx[t*64+b][n] = sum_k x[t,b,k] * W_gate[j, 1024+k] + bias
// C[M=32768, N=4096], K=1024.  BM=128, BN=64, BK=16, 256 threads.
// Thread tile: 8m x 4n, m packed in f32x2 pairs.
// ---------------------------------------------------------------
#define A_BM 128
#define A_BN 64
#define A_BK 16

__global__ void __launch_bounds__(256) input_gemm(
    const float* __restrict__ x,
    const float* __restrict__ Wf, const float* __restrict__ Wi,
    const float* __restrict__ Wo, const float* __restrict__ Wc,
    const float* __restrict__ bf, const float* __restrict__ bi,
    const float* __restrict__ bo, const float* __restrict__ bc)
{
    __shared__ __align__(16) float As[A_BK][132];  // [k][m], padded stride
    __shared__ __align__(16) float Bs[A_BK][68];   // [k][n]

    const int tid = threadIdx.x;
    const int bn  = blockIdx.x;           // 0..63
    const int bm  = blockIdx.y;           // 0..255
    const int n0g = bn * A_BN;            // global gate-column base
    const int gate = n0g >> 10;
    const int j0   = n0g & 1023;          // row base inside this gate's W
    const float* W    = (gate == 0) ? Wf : (gate == 1) ? Wi : (gate == 2) ? Wo : Wc;
    const float* bias = (gate == 0) ? bf : (gate == 1) ? bi : (gate == 2) ? bo : bc;
    const int r0 = bm * A_BM;

    const int nt = tid & 15;              // 0..15
    const int mt = tid >> 4;              // 0..15
    const int m0 = mt * 8;
    const int n0 = nt * 4;

    unsigned long long acc[4][4];         // [n][m-pair]
    #pragma unroll
    for (int i = 0; i < 4; i++)
        #pragma unroll
        for (int j = 0; j < 4; j++) acc[i][j] = 0ull;

    for (int k0 = 0; k0 < DIN; k0 += A_BK) {
        // load A tile: 128 rows x 16 k  (2 x float4 per thread)
        #pragma unroll
        for (int i = 0; i < 2; i++) {
            int idx = tid + i * 256;
            int m = idx >> 2, q = (idx & 3) * 4;
            float4 v = *(const float4*)&x[(size_t)(r0 + m) * DIN + k0 + q];
            As[q + 0][m] = v.x; As[q + 1][m] = v.y;
            As[q + 2][m] = v.z; As[q + 3][m] = v.w;
        }
        // load B tile: 64 rows (n) x 16 k  (1 x float4 per thread)
        {
            int n = tid >> 2, q = (tid & 3) * 4;
            float4 v = *(const float4*)&W[(size_t)(j0 + n) * DCAT + DIN + k0 + q];
            Bs[q + 0][n] = v.x; Bs[q + 1][n] = v.y;
            Bs[q + 2][n] = v.z; Bs[q + 3][n] = v.w;
        }
        __syncthreads();

        #pragma unroll
        for (int k = 0; k < A_BK; k++) {
            ulonglong2 a01 = *(const ulonglong2*)&As[k][m0];
            ulonglong2 a23 = *(const ulonglong2*)&As[k][m0 + 4];
            float4 bv = *(const float4*)&Bs[k][n0];
            unsigned long long bd0 = pack2(bv.x, bv.x);
            unsigned long long bd1 = pack2(bv.y, bv.y);
            unsigned long long bd2 = pack2(bv.z, bv.z);
            unsigned long long bd3 = pack2(bv.w, bv.w);
            acc[0][0] = fma2(a01.x, bd0, acc[0][0]);
            acc[0][1] = fma2(a01.y, bd0, acc[0][1]);
            acc[0][2] = fma2(a23.x, bd0, acc[0][2]);
            acc[0][3] = fma2(a23.y, bd0, acc[0][3]);
            acc[1][0] = fma2(a01.x, bd1, acc[1][0]);
            acc[1][1] = fma2(a01.y, bd1, acc[1][1]);
            acc[1][2] = fma2(a23.x, bd1, acc[1][2]);
            acc[1][3] = fma2(a23.y, bd1, acc[1][3]);
            acc[2][0] = fma2(a01.x, bd2, acc[2][0]);
            acc[2][1] = fma2(a01.y, bd2, acc[2][1]);
            acc[2][2] = fma2(a23.x, bd2, acc[2][2]);
            acc[2][3] = fma2(a23.y, bd2, acc[2][3]);
            acc[3][0] = fma2(a01.x, bd3, acc[3][0]);
            acc[3][1] = fma2(a01.y, bd3, acc[3][1]);
            acc[3][2] = fma2(a23.x, bd3, acc[3][2]);
            acc[3][3] = fma2(a23.y, bd3, acc[3][3]);
        }
        __syncthreads();
    }

    // epilogue: add bias, store float4 per (m)
    float b0 = bias[j0 + n0 + 0];
    float b1 = bias[j0 + n0 + 1];
    float b2 = bias[j0 + n0 + 2];
    float b3 = bias[j0 + n0 + 3];
    #pragma unroll
    for (int mp = 0; mp < 4; mp++) {
        float v0l, v0h, v1l, v1h, v2l, v2h, v3l, v3h;
        unpack2(acc[0][mp], v0l, v0h);
        unpack2(acc[1][mp], v1l, v1h);
        unpack2(acc[2][mp], v2l, v2h);
        unpack2(acc[3][mp], v3l, v3h);
        int mA = r0 + m0 + 2 * mp;
        float4 lo = make_float4(v0l + b0, v1l + b1, v2l + b2, v3l + b3);
        float4 hi = make_float4(v0h + b0, v1h + b1, v2h + b2, v3h + b3);
        *(float4*)&g_gx[(size_t)mA * NGATE + n0g + n0]       = lo;
        *(float4*)&g_gx[(size_t)(mA + 1) * NGATE + n0g + n0] = hi;
    }
}

// ---------------------------------------------------------------
// Phase B: one time step.
// gates_h[64, 4096] = h_{t-1}[64,1024] @ Wh^T, fused with gx add,
// activations, cell update, h write (to d_out[t]).
// Block: 8 latent dims x 4 gates (BN=32), BM=64(all batch), BK=16.
// 128 threads; thread tile 4m x 4gates (one latent j), m in f32x2 pairs.
// n-local layout: n = jloc*4 + gate  (so each thread owns all 4 gates of j)
// ---------------------------------------------------------------
#define S_BK 16

__global__ void __launch_bounds__(128) lstm_step(
    int t,
    const float* __restrict__ Wf, const float* __restrict__ Wi,
    const float* __restrict__ Wo, const float* __restrict__ Wc,
    float* __restrict__ out)
{
    __shared__ __align__(16) float As[S_BK][68];  // h tile [k][m], 64 m
    __shared__ __align__(16) float Bs[S_BK][36];  // W tile [k][n], 32 n

    const int tid = threadIdx.x;
    const int jb  = blockIdx.x * 8;       // latent base, 128 blocks
    const float* hprev = (t == 0) ? g_h0 : out + (size_t)(t - 1) * BATCH * DLAT;

    const int jl = tid & 7;               // latent within tile
    const int mt = tid >> 3;              // 0..15
    const int m0 = mt * 4;

    unsigned long long acc[4][2];         // [gate][m-pair]
    #pragma unroll
    for (int g = 0; g < 4; g++) { acc[g][0] = 0ull; acc[g][1] = 0ull; }

    for (int k0 = 0; k0 < DLAT; k0 += S_BK) {
        // load h tile: 64 m x 16 k (2 x float4 per thread)
        #pragma unroll
        for (int i = 0; i < 2; i++) {
            int idx = tid + i * 128;
            int m = idx >> 2, q = (idx & 3) * 4;
            float4 v = *(const float4*)&hprev[(size_t)m * DLAT + k0 + q];
            As[q + 0][m] = v.x; As[q + 1][m] = v.y;
            As[q + 2][m] = v.z; As[q + 3][m] = v.w;
        }
        // load W tile: 32 n x 16 k (1 x float4 per thread)
        {
            int n = tid >> 2, q = (tid & 3) * 4;
            int gate = n & 3, jloc = n >> 2;
            const float* W = (gate == 0) ? Wf : (gate == 1) ? Wi : (gate == 2) ? Wo : Wc;
            float4 v = *(const float4*)&W[(size_t)(jb + jloc) * DCAT + k0 + q];
            Bs[q + 0][n] = v.x; Bs[q + 1][n] = v.y;
            Bs[q + 2][n] = v.z; Bs[q + 3][n] = v.w;
        }
        __syncthreads();

        #pragma unroll
        for (int k = 0; k < S_BK; k++) {
            ulonglong2 a = *(const ulonglong2*)&As[k][m0];
            float4 bv = *(const float4*)&Bs[k][jl * 4];
            unsigned long long b0 = pack2(bv.x, bv.x);
            unsigned long long b1 = pack2(bv.y, bv.y);
            unsigned long long b2 = pack2(bv.z, bv.z);
            unsigned long long b3 = pack2(bv.w, bv.w);
            acc[0][0] = fma2(a.x, b0, acc[0][0]);
            acc[0][1] = fma2(a.y, b0, acc[0][1]);
            acc[1][0] = fma2(a.x, b1, acc[1][0]);
            acc[1][1] = fma2(a.y, b1, acc[1][1]);
            acc[2][0] = fma2(a.x, b2, acc[2][0]);
            acc[2][1] = fma2(a.y, b2, acc[2][1]);
            acc[3][0] = fma2(a.x, b3, acc[3][0]);
            acc[3][1] = fma2(a.y, b3, acc[3][1]);
        }
        __syncthreads();
    }

    // fused epilogue
    const float* gx = g_gx + (size_t)t * BATCH * NGATE;
    const int j = jb + jl;
    #pragma unroll
    for (int mp = 0; mp < 2; mp++) {
        float gf[2], gi[2], go[2], gg[2];
        unpack2(acc[0][mp], gf[0], gf[1]);
        unpack2(acc[1][mp], gi[0], gi[1]);
        unpack2(acc[2][mp], go[0], go[1]);
        unpack2(acc[3][mp], gg[0], gg[1]);
        #pragma unroll
        for (int l = 0; l < 2; l++) {
            int m = m0 + mp * 2 + l;
            size_t gb = (size_t)m * NGATE + j;
            float vf = sigmoidf_(gf[l] + gx[gb]);
            float vi = sigmoidf_(gi[l] + gx[gb + 1024]);
            float vo = sigmoidf_(go[l] + gx[gb + 2048]);
            float vg = tanhf(gg[l] + gx[gb + 3072]);
            size_t ci = (size_t)m * DLAT + j;
            float c = vf * g_c[ci] + vi * vg;
            g_c[ci] = c;
            out[(size_t)(t * BATCH + m) * DLAT + j] = vo * tanhf(c);
        }
    }
}

// ---------------------------------------------------------------
extern "C" void kernel_launch(void* const* d_in, const int* in_sizes, int n_in,
                              void* d_out, int out_size)
{
    const float* x  = (const float*)d_in[0];
    const float* Wf = (const float*)d_in[1];
    const float* bf = (const float*)d_in[2];
    const float* Wi = (const float*)d_in[3];
    const float* bi = (const float*)d_in[4];
    const float* Wo = (const float*)d_in[5];
    const float* bo = (const float*)d_in[6];
    const float* Wc = (const float*)d_in[7];
    const float* bc = (const float*)d_in[8];
    float* out = (float*)d_out;

    init_state<<<256, 256>>>();

    dim3 gridA(NGATE / A_BN, (SEQ * BATCH) / A_BM);   // (64, 256)
    input_gemm<<<gridA, 256>>>(x, Wf, Wi, Wo, Wc, bf, bi, bo, bc);

    for (int t = 0; t < SEQ; t++) {
        lstm_step<<<DLAT / 8, 128>>>(t, Wf, Wi, Wo, Wc, out);
    }
}

// round 3
// speedup vs baseline: 1.6490x; 1.6490x over previous
#include <cuda_runtime.h>
#include <math.h>
#include <stdint.h>

#define SEQ   512
#define BATCH 64
#define DIN   1024
#define DLAT  1024
#define DCAT  2048
#define NGATE 4096   // 4 * DLAT

// Scratch (allocation-free rule: __device__ globals)
__device__ float g_gx[(size_t)SEQ * BATCH * NGATE];  // precomputed x-side gates (+bias)
__device__ float g_h0[BATCH * DLAT];                 // zero h_{-1}
__device__ float g_c [BATCH * DLAT];                 // cell state (block-exclusive j ranges)

// ---------- packed f32x2 helpers (Blackwell: 2x fp32 FMA rate) ----------
__device__ __forceinline__ unsigned long long pack2(float lo, float hi) {
    unsigned long long r;
    asm("mov.b64 %0, {%1, %2};" : "=l"(r) : "f"(lo), "f"(hi));
    return r;
}
__device__ __forceinline__ void unpack2(unsigned long long v, float& lo, float& hi) {
    asm("mov.b64 {%0, %1}, %2;" : "=f"(lo), "=f"(hi) : "l"(v));
}
__device__ __forceinline__ unsigned long long fma2(unsigned long long a,
                                                   unsigned long long b,
                                                   unsigned long long c) {
    unsigned long long d;
    asm("fma.rn.f32x2 %0, %1, %2, %3;" : "=l"(d) : "l"(a), "l"(b), "l"(c));
    return d;
}

__device__ __forceinline__ float sigmoidf_(float x) {
    return 1.0f / (1.0f + __expf(-x));
}

// ---------------------------------------------------------------
// init: zero h_{-1} and c (must run every kernel_launch call)
// ---------------------------------------------------------------
__global__ void init_state() {
    int i = blockIdx.x * blockDim.x + threadIdx.x;
    if (i < BATCH * DLAT) { g_h0[i] = 0.0f; g_c[i] = 0.0f; }
}

// ---------------------------------------------------------------
// Phase A: gx[t*64+b][n] = sum_k x[t,b,k] * W_gate[j, 1024+k] + bias
// C[M=32768, N=4096], K=1024.  BM=128, BN=64, BK=16, 256 threads.
// ---------------------------------------------------------------
#define A_BM 128
#define A_BN 64
#define A_BK 16

__global__ void __launch_bounds__(256) input_gemm(
    const float* __restrict__ x,
    const float* __restrict__ Wf, const float* __restrict__ Wi,
    const float* __restrict__ Wo, const float* __restrict__ Wc,
    const float* __restrict__ bf, const float* __restrict__ bi,
    const float* __restrict__ bo, const float* __restrict__ bc)
{
    __shared__ __align__(16) float As[A_BK][132];
    __shared__ __align__(16) float Bs[A_BK][68];

    const int tid = threadIdx.x;
    const int bn  = blockIdx.x;
    const int bm  = blockIdx.y;
    const int n0g = bn * A_BN;
    const int gate = n0g >> 10;
    const int j0   = n0g & 1023;
    const float* W    = (gate == 0) ? Wf : (gate == 1) ? Wi : (gate == 2) ? Wo : Wc;
    const float* bias = (gate == 0) ? bf : (gate == 1) ? bi : (gate == 2) ? bo : bc;
    const int r0 = bm * A_BM;

    const int nt = tid & 15;
    const int mt = tid >> 4;
    const int m0 = mt * 8;
    const int n0 = nt * 4;

    unsigned long long acc[4][4];
    #pragma unroll
    for (int i = 0; i < 4; i++)
        #pragma unroll
        for (int j = 0; j < 4; j++) acc[i][j] = 0ull;

    for (int k0 = 0; k0 < DIN; k0 += A_BK) {
        #pragma unroll
        for (int i = 0; i < 2; i++) {
            int idx = tid + i * 256;
            int m = idx >> 2, q = (idx & 3) * 4;
            float4 v = *(const float4*)&x[(size_t)(r0 + m) * DIN + k0 + q];
            As[q + 0][m] = v.x; As[q + 1][m] = v.y;
            As[q + 2][m] = v.z; As[q + 3][m] = v.w;
        }
        {
            int n = tid >> 2, q = (tid & 3) * 4;
            float4 v = *(const float4*)&W[(size_t)(j0 + n) * DCAT + DIN + k0 + q];
            Bs[q + 0][n] = v.x; Bs[q + 1][n] = v.y;
            Bs[q + 2][n] = v.z; Bs[q + 3][n] = v.w;
        }
        __syncthreads();

        #pragma unroll
        for (int k = 0; k < A_BK; k++) {
            ulonglong2 a01 = *(const ulonglong2*)&As[k][m0];
            ulonglong2 a23 = *(const ulonglong2*)&As[k][m0 + 4];
            float4 bv = *(const float4*)&Bs[k][n0];
            unsigned long long bd0 = pack2(bv.x, bv.x);
            unsigned long long bd1 = pack2(bv.y, bv.y);
            unsigned long long bd2 = pack2(bv.z, bv.z);
            unsigned long long bd3 = pack2(bv.w, bv.w);
            acc[0][0] = fma2(a01.x, bd0, acc[0][0]);
            acc[0][1] = fma2(a01.y, bd0, acc[0][1]);
            acc[0][2] = fma2(a23.x, bd0, acc[0][2]);
            acc[0][3] = fma2(a23.y, bd0, acc[0][3]);
            acc[1][0] = fma2(a01.x, bd1, acc[1][0]);
            acc[1][1] = fma2(a01.y, bd1, acc[1][1]);
            acc[1][2] = fma2(a23.x, bd1, acc[1][2]);
            acc[1][3] = fma2(a23.y, bd1, acc[1][3]);
            acc[2][0] = fma2(a01.x, bd2, acc[2][0]);
            acc[2][1] = fma2(a01.y, bd2, acc[2][1]);
            acc[2][2] = fma2(a23.x, bd2, acc[2][2]);
            acc[2][3] = fma2(a23.y, bd2, acc[2][3]);
            acc[3][0] = fma2(a01.x, bd3, acc[3][0]);
            acc[3][1] = fma2(a01.y, bd3, acc[3][1]);
            acc[3][2] = fma2(a23.x, bd3, acc[3][2]);
            acc[3][3] = fma2(a23.y, bd3, acc[3][3]);
        }
        __syncthreads();
    }

    float b0 = bias[j0 + n0 + 0];
    float b1 = bias[j0 + n0 + 1];
    float b2 = bias[j0 + n0 + 2];
    float b3 = bias[j0 + n0 + 3];
    #pragma unroll
    for (int mp = 0; mp < 4; mp++) {
        float v0l, v0h, v1l, v1h, v2l, v2h, v3l, v3h;
        unpack2(acc[0][mp], v0l, v0h);
        unpack2(acc[1][mp], v1l, v1h);
        unpack2(acc[2][mp], v2l, v2h);
        unpack2(acc[3][mp], v3l, v3h);
        int mA = r0 + m0 + 2 * mp;
        float4 lo = make_float4(v0l + b0, v1l + b1, v2l + b2, v3l + b3);
        float4 hi = make_float4(v0h + b0, v1h + b1, v2h + b2, v3h + b3);
        *(float4*)&g_gx[(size_t)mA * NGATE + n0g + n0]       = lo;
        *(float4*)&g_gx[(size_t)(mA + 1) * NGATE + n0g + n0] = hi;
    }
}

// ---------------------------------------------------------------
// Phase B v2: one time step, 128 blocks x 256 threads.
// In-block split-K: warp-group kg in {0,1} covers K = 512 each for the
// same [64 batch x 32 n] tile (8 latents x 4 gates, n = jloc*4+gate).
// Software-pipelined: prefetch next BK=32 tile to regs during compute,
// double-buffered smem, one barrier per tile. Final cross-group add via
// shared, then fused LSTM epilogue.
// ---------------------------------------------------------------
#define S_BK 32
#define S_NT 16   // (1024/2) / 32 tiles per k-group

__global__ void __launch_bounds__(256) lstm_step(
    int t,
    const float* __restrict__ Wf, const float* __restrict__ Wi,
    const float* __restrict__ Wo, const float* __restrict__ Wc,
    float* __restrict__ out)
{
    __shared__ __align__(16) float As[2][2][S_BK][68];  // [kg][buf][k][m]
    __shared__ __align__(16) float Bs[2][2][S_BK][36];  // [kg][buf][k][n]

    const int tid  = threadIdx.x;
    const int kg   = tid >> 7;        // k-group 0/1
    const int ltid = tid & 127;
    const int jb   = blockIdx.x * 8;  // latent base
    const float* hprev = (t == 0) ? g_h0 : out + (size_t)(t - 1) * BATCH * DLAT;

    const int jl = ltid & 7;
    const int mt = ltid >> 3;
    const int m0 = mt * 4;
    const int kbase0 = kg * 512;

    // prefetch registers
    float4 pa[4];   // A tile: 64m x 32k / 128thr = 4 float4
    float4 pb[2];   // B tile: 32n x 32k / 128thr = 2 float4

    unsigned long long acc[4][2];
    #pragma unroll
    for (int g = 0; g < 4; g++) { acc[g][0] = 0ull; acc[g][1] = 0ull; }

    // ---- tile load (global -> regs) ----
    #define LOAD_TILE(TILE) do {                                              \
        int kb = kbase0 + (TILE) * S_BK;                                      \
        _Pragma("unroll")                                                     \
        for (int i = 0; i < 4; i++) {                                         \
            int e = ltid + i * 128;                                           \
            int m = e >> 3, q = (e & 7) * 4;                                  \
            pa[i] = *(const float4*)&hprev[(size_t)m * DLAT + kb + q];        \
        }                                                                     \
        _Pragma("unroll")                                                     \
        for (int i = 0; i < 2; i++) {                                         \
            int e = ltid + i * 128;                                           \
            int n = e >> 3, q = (e & 7) * 4;                                  \
            int gate = n & 3, jloc = n >> 2;                                  \
            const float* W = (gate == 0) ? Wf : (gate == 1) ? Wi              \
                           : (gate == 2) ? Wo : Wc;                           \
            pb[i] = *(const float4*)&W[(size_t)(jb + jloc) * DCAT + kb + q];  \
        }                                                                     \
    } while (0)

    // ---- tile store (regs -> smem[buf]) ----
    #define STORE_TILE(BUF) do {                                              \
        _Pragma("unroll")                                                     \
        for (int i = 0; i < 4; i++) {                                         \
            int e = ltid + i * 128;                                           \
            int m = e >> 3, q = (e & 7) * 4;                                  \
            As[kg][BUF][q + 0][m] = pa[i].x;                                  \
            As[kg][BUF][q + 1][m] = pa[i].y;                                  \
            As[kg][BUF][q + 2][m] = pa[i].z;                                  \
            As[kg][BUF][q + 3][m] = pa[i].w;                                  \
        }                                                                     \
        _Pragma("unroll")                                                     \
        for (int i = 0; i < 2; i++) {                                         \
            int e = ltid + i * 128;                                           \
            int n = e >> 3, q = (e & 7) * 4;                                  \
            Bs[kg][BUF][q + 0][n] = pb[i].x;                                  \
            Bs[kg][BUF][q + 1][n] = pb[i].y;                                  \
            Bs[kg][BUF][q + 2][n] = pb[i].z;                                  \
            Bs[kg][BUF][q + 3][n] = pb[i].w;                                  \
        }                                                                     \
    } while (0)

    LOAD_TILE(0);
    STORE_TILE(0);
    __syncthreads();

    for (int tile = 0; tile < S_NT; tile++) {
        const int buf = tile & 1;
        if (tile + 1 < S_NT) LOAD_TILE(tile + 1);   // overlaps with compute

        #pragma unroll
        for (int k = 0; k < S_BK; k++) {
            ulonglong2 a = *(const ulonglong2*)&As[kg][buf][k][m0];
            float4 bv = *(const float4*)&Bs[kg][buf][k][jl * 4];
            unsigned long long b0 = pack2(bv.x, bv.x);
            unsigned long long b1 = pack2(bv.y, bv.y);
            unsigned long long b2 = pack2(bv.z, bv.z);
            unsigned long long b3 = pack2(bv.w, bv.w);
            acc[0][0] = fma2(a.x, b0, acc[0][0]);
            acc[0][1] = fma2(a.y, b0, acc[0][1]);
            acc[1][0] = fma2(a.x, b1, acc[1][0]);
            acc[1][1] = fma2(a.y, b1, acc[1][1]);
            acc[2][0] = fma2(a.x, b2, acc[2][0]);
            acc[2][1] = fma2(a.y, b2, acc[2][1]);
            acc[3][0] = fma2(a.x, b3, acc[3][0]);
            acc[3][1] = fma2(a.y, b3, acc[3][1]);
        }

        if (tile + 1 < S_NT) STORE_TILE((tile + 1) & 1);
        __syncthreads();
    }

    // ---- cross-group reduction (reuse As as scratch) ----
    float vals[4][4];
    #pragma unroll
    for (int g = 0; g < 4; g++) {
        unpack2(acc[g][0], vals[g][0], vals[g][1]);
        unpack2(acc[g][1], vals[g][2], vals[g][3]);
    }

    float* red = (float*)As;   // 128 * 17 floats, padded stride
    if (kg == 1) {
        #pragma unroll
        for (int g = 0; g < 4; g++)
            #pragma unroll
            for (int i = 0; i < 4; i++)
                red[ltid * 17 + g * 4 + i] = vals[g][i];
    }
    __syncthreads();

    if (kg == 0) {
        #pragma unroll
        for (int g = 0; g < 4; g++)
            #pragma unroll
            for (int i = 0; i < 4; i++)
                vals[g][i] += red[ltid * 17 + g * 4 + i];

        // ---- fused LSTM epilogue ----
        const float* gx = g_gx + (size_t)t * BATCH * NGATE;
        const int j = jb + jl;
        #pragma unroll
        for (int i = 0; i < 4; i++) {
            int m = m0 + i;
            size_t gb = (size_t)m * NGATE + j;
            float vf = sigmoidf_(vals[0][i] + gx[gb]);
            float vi = sigmoidf_(vals[1][i] + gx[gb + 1024]);
            float vo = sigmoidf_(vals[2][i] + gx[gb + 2048]);
            float vg = tanhf(vals[3][i] + gx[gb + 3072]);
            size_t ci = (size_t)m * DLAT + j;
            float c = vf * g_c[ci] + vi * vg;
            g_c[ci] = c;
            out[(size_t)(t * BATCH + m) * DLAT + j] = vo * tanhf(c);
        }
    }
}

// ---------------------------------------------------------------
extern "C" void kernel_launch(void* const* d_in, const int* in_sizes, int n_in,
                              void* d_out, int out_size)
{
    const float* x  = (const float*)d_in[0];
    const float* Wf = (const float*)d_in[1];
    const float* bf = (const float*)d_in[2];
    const float* Wi = (const float*)d_in[3];
    const float* bi = (const float*)d_in[4];
    const float* Wo = (const float*)d_in[5];
    const float* bo = (const float*)d_in[6];
    const float* Wc = (const float*)d_in[7];
    const float* bc = (const float*)d_in[8];
    float* out = (float*)d_out;

    init_state<<<256, 256>>>();

    dim3 gridA(NGATE / A_BN, (SEQ * BATCH) / A_BM);   // (64, 256)
    input_gemm<<<gridA, 256>>>(x, Wf, Wi, Wo, Wc, bf, bi, bo, bc);

    for (int t = 0; t < SEQ; t++) {
        lstm_step<<<DLAT / 8, 256>>>(t, Wf, Wi, Wo, Wc, out);
    }
}

// round 5
// speedup vs baseline: 2.4690x; 1.4972x over previous
#include <cuda_runtime.h>
#include <cuda_bf16.h>
#include <math.h>
#include <stdint.h>

#define SEQ   512
#define BATCH 64
#define DIN   1024
#define DLAT  1024
#define DCAT  2048
#define NGATE 4096

// ---------------- device scratch (no allocs allowed) ----------------
__device__ float g_gx[(size_t)SEQ * BATCH * NGATE];   // x-side gates (+bias)
__device__ float g_c [BATCH * DLAT];                  // cell state
// bf16 split weight images, rows reordered: wrow = j*4 + gate, cols = k (h-part)
__device__ __nv_bfloat16 g_whi[(size_t)NGATE * DLAT];
__device__ __nv_bfloat16 g_wlo[(size_t)NGATE * DLAT];
// bf16 split h, double buffered: [buf][batch][k]
__device__ __nv_bfloat16 g_hhi[2][BATCH * DLAT];
__device__ __nv_bfloat16 g_hlo[2][BATCH * DLAT];

__device__ __forceinline__ float sigmoidf_(float x) { return 1.0f / (1.0f + __expf(-x)); }

__device__ __forceinline__ uint32_t smem_u32(const void* p) {
    uint32_t a;
    asm("{ .reg .u64 t; cvta.to.shared.u64 t, %1; cvt.u32.u64 %0, t; }" : "=r"(a) : "l"(p));
    return a;
}

// ---------------------------------------------------------------
__global__ void init_state() {
    int i = blockIdx.x * blockDim.x + threadIdx.x;
    if (i < BATCH * DLAT) {
        g_c[i] = 0.0f;
        g_hhi[0][i] = __float2bfloat16(0.0f);
        g_hlo[0][i] = __float2bfloat16(0.0f);
    }
}

// Build split weight images (h-part of W, cols [0,1024))
__global__ void wsplit_build(const float* __restrict__ Wf, const float* __restrict__ Wi,
                             const float* __restrict__ Wo, const float* __restrict__ Wc) {
    int idx = blockIdx.x * blockDim.x + threadIdx.x;   // 4096*1024
    int wrow = idx >> 10, k = idx & 1023;
    int j = wrow >> 2, gate = wrow & 3;
    const float* W = (gate == 0) ? Wf : (gate == 1) ? Wi : (gate == 2) ? Wo : Wc;
    float v = W[(size_t)j * DCAT + k];
    __nv_bfloat16 hi = __float2bfloat16(v);
    __nv_bfloat16 lo = __float2bfloat16(v - __bfloat162float(hi));
    g_whi[(size_t)wrow * DLAT + k] = hi;
    g_wlo[(size_t)wrow * DLAT + k] = lo;
}

// ---------------------------------------------------------------
// Phase A (unchanged): gx = x @ Wx^T + b, fp32 f32x2 SIMT
// ---------------------------------------------------------------
__device__ __forceinline__ unsigned long long pack2(float lo, float hi) {
    unsigned long long r;
    asm("mov.b64 %0, {%1, %2};" : "=l"(r) : "f"(lo), "f"(hi));
    return r;
}
__device__ __forceinline__ void unpack2(unsigned long long v, float& lo, float& hi) {
    asm("mov.b64 {%0, %1}, %2;" : "=f"(lo), "=f"(hi) : "l"(v));
}
__device__ __forceinline__ unsigned long long fma2(unsigned long long a,
                                                   unsigned long long b,
                                                   unsigned long long c) {
    unsigned long long d;
    asm("fma.rn.f32x2 %0, %1, %2, %3;" : "=l"(d) : "l"(a), "l"(b), "l"(c));
    return d;
}

#define A_BM 128
#define A_BN 64
#define A_BK 16

__global__ void __launch_bounds__(256) input_gemm(
    const float* __restrict__ x,
    const float* __restrict__ Wf, const float* __restrict__ Wi,
    const float* __restrict__ Wo, const float* __restrict__ Wc,
    const float* __restrict__ bf, const float* __restrict__ bi,
    const float* __restrict__ bo, const float* __restrict__ bc)
{
    __shared__ __align__(16) float As[A_BK][132];
    __shared__ __align__(16) float Bs[A_BK][68];

    const int tid = threadIdx.x;
    const int n0g = blockIdx.x * A_BN;
    const int gate = n0g >> 10;
    const int j0   = n0g & 1023;
    const float* W    = (gate == 0) ? Wf : (gate == 1) ? Wi : (gate == 2) ? Wo : Wc;
    const float* bias = (gate == 0) ? bf : (gate == 1) ? bi : (gate == 2) ? bo : bc;
    const int r0 = blockIdx.y * A_BM;

    const int nt = tid & 15, mt = tid >> 4;
    const int m0 = mt * 8, n0 = nt * 4;

    unsigned long long acc[4][4];
    #pragma unroll
    for (int i = 0; i < 4; i++)
        #pragma unroll
        for (int j = 0; j < 4; j++) acc[i][j] = 0ull;

    for (int k0 = 0; k0 < DIN; k0 += A_BK) {
        #pragma unroll
        for (int i = 0; i < 2; i++) {
            int idx = tid + i * 256;
            int m = idx >> 2, q = (idx & 3) * 4;
            float4 v = *(const float4*)&x[(size_t)(r0 + m) * DIN + k0 + q];
            As[q + 0][m] = v.x; As[q + 1][m] = v.y;
            As[q + 2][m] = v.z; As[q + 3][m] = v.w;
        }
        {
            int n = tid >> 2, q = (tid & 3) * 4;
            float4 v = *(const float4*)&W[(size_t)(j0 + n) * DCAT + DIN + k0 + q];
            Bs[q + 0][n] = v.x; Bs[q + 1][n] = v.y;
            Bs[q + 2][n] = v.z; Bs[q + 3][n] = v.w;
        }
        __syncthreads();

        #pragma unroll
        for (int k = 0; k < A_BK; k++) {
            ulonglong2 a01 = *(const ulonglong2*)&As[k][m0];
            ulonglong2 a23 = *(const ulonglong2*)&As[k][m0 + 4];
            float4 bv = *(const float4*)&Bs[k][n0];
            unsigned long long bd0 = pack2(bv.x, bv.x);
            unsigned long long bd1 = pack2(bv.y, bv.y);
            unsigned long long bd2 = pack2(bv.z, bv.z);
            unsigned long long bd3 = pack2(bv.w, bv.w);
            acc[0][0] = fma2(a01.x, bd0, acc[0][0]);
            acc[0][1] = fma2(a01.y, bd0, acc[0][1]);
            acc[0][2] = fma2(a23.x, bd0, acc[0][2]);
            acc[0][3] = fma2(a23.y, bd0, acc[0][3]);
            acc[1][0] = fma2(a01.x, bd1, acc[1][0]);
            acc[1][1] = fma2(a01.y, bd1, acc[1][1]);
            acc[1][2] = fma2(a23.x, bd1, acc[1][2]);
            acc[1][3] = fma2(a23.y, bd1, acc[1][3]);
            acc[2][0] = fma2(a01.x, bd2, acc[2][0]);
            acc[2][1] = fma2(a01.y, bd2, acc[2][1]);
            acc[2][2] = fma2(a23.x, bd2, acc[2][2]);
            acc[2][3] = fma2(a23.y, bd2, acc[2][3]);
            acc[3][0] = fma2(a01.x, bd3, acc[3][0]);
            acc[3][1] = fma2(a01.y, bd3, acc[3][1]);
            acc[3][2] = fma2(a23.x, bd3, acc[3][2]);
            acc[3][3] = fma2(a23.y, bd3, acc[3][3]);
        }
        __syncthreads();
    }

    float b0 = bias[j0 + n0 + 0], b1 = bias[j0 + n0 + 1];
    float b2 = bias[j0 + n0 + 2], b3 = bias[j0 + n0 + 3];
    #pragma unroll
    for (int mp = 0; mp < 4; mp++) {
        float v0l, v0h, v1l, v1h, v2l, v2h, v3l, v3h;
        unpack2(acc[0][mp], v0l, v0h);
        unpack2(acc[1][mp], v1l, v1h);
        unpack2(acc[2][mp], v2l, v2h);
        unpack2(acc[3][mp], v3l, v3h);
        int mA = r0 + m0 + 2 * mp;
        float4 lo = make_float4(v0l + b0, v1l + b1, v2l + b2, v3l + b3);
        float4 hi = make_float4(v0h + b0, v1h + b1, v2h + b2, v3h + b3);
        *(float4*)&g_gx[(size_t)mA * NGATE + n0g + n0]       = lo;
        *(float4*)&g_gx[(size_t)(mA + 1) * NGATE + n0g + n0] = hi;
    }
}

// ---------------------------------------------------------------
// Phase B: HMMA step. 128 blocks x 256 threads (8 warps).
// Block covers 32 gate-rows (wrow = j*4+gate, j in [jb, jb+8)) x 64 batch.
// Split-bf16 GEMM: acc += Whi*hhi + Whi*hlo + Wlo*hhi  (fp32 accum).
// cp.async double-buffered K chunks of 64.
// ---------------------------------------------------------------
#define S_BK   64
#define S_NCH  (DLAT / S_BK)      // 16
#define ASTRIDE 72                // bf16 elems per smem row (64 + 8 pad)
#define A_SPL   (32 * ASTRIDE * 2)          // 4608 B per A split
#define B_SPL   (64 * ASTRIDE * 2)          // 9216 B per B split
#define A_BUF   (2 * A_SPL)                 // 9216
#define B_BUF   (2 * B_SPL)                 // 18432
#define B_BASE  (2 * A_BUF)                 // 18432
#define DSMEM_BYTES (2 * A_BUF + 2 * B_BUF) // 55296

#define CP16(dst, src) \
    asm volatile("cp.async.cg.shared.global [%0], [%1], 16;" :: "r"(dst), "l"(src))
#define CP_COMMIT() asm volatile("cp.async.commit_group;")
#define CP_WAIT1()  asm volatile("cp.async.wait_group 1;")
#define CP_WAIT0()  asm volatile("cp.async.wait_group 0;")

__device__ __forceinline__ void mma_bf16(float c[4], uint32_t a0, uint32_t a1,
                                         uint32_t a2, uint32_t a3,
                                         uint32_t b0, uint32_t b1) {
    asm volatile("mma.sync.aligned.m16n8k16.row.col.f32.bf16.bf16.f32 "
        "{%0,%1,%2,%3}, {%4,%5,%6,%7}, {%8,%9}, {%0,%1,%2,%3};"
        : "+f"(c[0]), "+f"(c[1]), "+f"(c[2]), "+f"(c[3])
        : "r"(a0), "r"(a1), "r"(a2), "r"(a3), "r"(b0), "r"(b1));
}

__global__ void __launch_bounds__(256) lstm_step_mma(int t, float* __restrict__ out)
{
    extern __shared__ __align__(16) uint8_t dsm[];
    const uint32_t sb = smem_u32(dsm);

    const int tid  = threadIdx.x;
    const int wid  = tid >> 5;
    const int lane = tid & 31;
    const int wm   = wid & 1;          // m-tile 0/1 (16 rows each)
    const int wn   = wid >> 1;         // batch group 0..3 (16 each)
    const int n0   = wn * 16;
    const int gid  = lane >> 2;        // groupID
    const int tig  = lane & 3;

    const int rb = t & 1;
    const int r0 = blockIdx.x * 32;    // global wrow base
    const int jb = blockIdx.x * 8;     // latent base
    const __nv_bfloat16* hhi = g_hhi[rb];
    const __nv_bfloat16* hlo = g_hlo[rb];

    // ---- cp.async tile fill ----
    #define FILL(BUF, K0) do {                                                   \
        _Pragma("unroll")                                                        \
        for (int i = 0; i < 2; i++) {                                            \
            int op = tid + i * 256;                                              \
            int s = op >> 8, row = (op >> 3) & 31, seg = op & 7;                 \
            const __nv_bfloat16* src = (s ? g_wlo : g_whi)                       \
                + (size_t)(r0 + row) * DLAT + (K0) + seg * 8;                    \
            uint32_t dst = sb + (BUF) * A_BUF + s * A_SPL + row * (ASTRIDE*2) + seg * 16; \
            CP16(dst, src);                                                      \
        }                                                                        \
        _Pragma("unroll")                                                        \
        for (int i = 0; i < 4; i++) {                                            \
            int op = tid + i * 256;                                              \
            int s = op >> 9, row = (op >> 3) & 63, seg = op & 7;                 \
            const __nv_bfloat16* src = (s ? hlo : hhi)                           \
                + (size_t)row * DLAT + (K0) + seg * 8;                           \
            uint32_t dst = sb + B_BASE + (BUF) * B_BUF + s * B_SPL + row * (ASTRIDE*2) + seg * 16; \
            CP16(dst, src);                                                      \
        }                                                                        \
        CP_COMMIT();                                                             \
    } while (0)

    float acc[2][4];
    #pragma unroll
    for (int nt = 0; nt < 2; nt++)
        #pragma unroll
        for (int i = 0; i < 4; i++) acc[nt][i] = 0.0f;

    FILL(0, 0);
    FILL(1, S_BK);

    for (int c = 0; c < S_NCH; c++) {
        if (c + 2 < S_NCH) CP_WAIT1(); else CP_WAIT0();
        __syncthreads();
        const int buf = c & 1;
        const uint32_t Ahi = sb + buf * A_BUF;
        const uint32_t Alo = Ahi + A_SPL;
        const uint32_t Bhi = sb + B_BASE + buf * B_BUF;
        const uint32_t Blo = Bhi + B_SPL;

        #pragma unroll
        for (int q = 0; q < 4; q++) {
            const int kk = q * 16;
            // A frags (rows wm*16+gid, +8; k = kk+tig*2, +8)
            const uint32_t ar0 = (wm * 16 + gid) * (ASTRIDE * 2) + (kk + tig * 2) * 2;
            const uint32_t ar1 = ar0 + 8 * (ASTRIDE * 2);
            uint32_t ah0 = *(const uint32_t*)(dsm + (Ahi - sb) + ar0);
            uint32_t ah1 = *(const uint32_t*)(dsm + (Ahi - sb) + ar1);
            uint32_t ah2 = *(const uint32_t*)(dsm + (Ahi - sb) + ar0 + 16);
            uint32_t ah3 = *(const uint32_t*)(dsm + (Ahi - sb) + ar1 + 16);
            uint32_t al0 = *(const uint32_t*)(dsm + (Alo - sb) + ar0);
            uint32_t al1 = *(const uint32_t*)(dsm + (Alo - sb) + ar1);
            uint32_t al2 = *(const uint32_t*)(dsm + (Alo - sb) + ar0 + 16);
            uint32_t al3 = *(const uint32_t*)(dsm + (Alo - sb) + ar1 + 16);
            #pragma unroll
            for (int nt = 0; nt < 2; nt++) {
                const uint32_t br = (n0 + nt * 8 + gid) * (ASTRIDE * 2) + (kk + tig * 2) * 2;
                uint32_t bh0 = *(const uint32_t*)(dsm + (Bhi - sb) + br);
                uint32_t bh1 = *(const uint32_t*)(dsm + (Bhi - sb) + br + 16);
                uint32_t bl0 = *(const uint32_t*)(dsm + (Blo - sb) + br);
                uint32_t bl1 = *(const uint32_t*)(dsm + (Blo - sb) + br + 16);
                mma_bf16(acc[nt], ah0, ah1, ah2, ah3, bh0, bh1);
                mma_bf16(acc[nt], ah0, ah1, ah2, ah3, bl0, bl1);
                mma_bf16(acc[nt], al0, al1, al2, al3, bh0, bh1);
            }
        }
        __syncthreads();
        if (c + 2 < S_NCH) FILL(buf, (c + 2) * S_BK);
    }

    // ---- exchange via smem: ex[32 rows][64 batch], stride 65 ----
    float* ex = (float*)dsm;
    #pragma unroll
    for (int nt = 0; nt < 2; nt++) {
        int R0 = wm * 16 + gid, C0 = n0 + nt * 8 + tig * 2;
        ex[R0 * 65 + C0]           = acc[nt][0];
        ex[R0 * 65 + C0 + 1]       = acc[nt][1];
        ex[(R0 + 8) * 65 + C0]     = acc[nt][2];
        ex[(R0 + 8) * 65 + C0 + 1] = acc[nt][3];
    }
    __syncthreads();

    // ---- fused LSTM epilogue: 512 (j,m) pairs, 2 per thread ----
    const float* gx = g_gx + (size_t)t * BATCH * NGATE;
    __nv_bfloat16* hwh = g_hhi[rb ^ 1];
    __nv_bfloat16* hwl = g_hlo[rb ^ 1];
    #pragma unroll
    for (int p = 0; p < 2; p++) {
        int q = tid * 2 + p;
        int m = q & 63, jl = q >> 6;
        int j = jb + jl;
        float sf = ex[(jl * 4 + 0) * 65 + m];
        float si = ex[(jl * 4 + 1) * 65 + m];
        float so = ex[(jl * 4 + 2) * 65 + m];
        float sg = ex[(jl * 4 + 3) * 65 + m];
        size_t gxb = (size_t)m * NGATE + j;
        float vf = sigmoidf_(sf + gx[gxb]);
        float vi = sigmoidf_(si + gx[gxb + 1024]);
        float vo = sigmoidf_(so + gx[gxb + 2048]);
        float vg = tanhf(sg + gx[gxb + 3072]);
        size_t ci = (size_t)m * DLAT + j;
        float cc = vf * g_c[ci] + vi * vg;
        g_c[ci] = cc;
        float h = vo * tanhf(cc);
        out[((size_t)t * BATCH + m) * DLAT + j] = h;
        __nv_bfloat16 hh = __float2bfloat16(h);
        __nv_bfloat16 hl = __float2bfloat16(h - __bfloat162float(hh));
        hwh[ci] = hh;
        hwl[ci] = hl;
    }
}

// ---------------------------------------------------------------
extern "C" void kernel_launch(void* const* d_in, const int* in_sizes, int n_in,
                              void* d_out, int out_size)
{
    const float* x  = (const float*)d_in[0];
    const float* Wf = (const float*)d_in[1];
    const float* bf = (const float*)d_in[2];
    const float* Wi = (const float*)d_in[3];
    const float* bi = (const float*)d_in[4];
    const float* Wo = (const float*)d_in[5];
    const float* bo = (const float*)d_in[6];
    const float* Wc = (const float*)d_in[7];
    const float* bc = (const float*)d_in[8];
    float* out = (float*)d_out;

    static int smem_set = 0;
    if (!smem_set) {
        cudaFuncSetAttribute(lstm_step_mma, cudaFuncAttributeMaxDynamicSharedMemorySize,
                             DSMEM_BYTES);
        smem_set = 1;
    }

    init_state<<<256, 256>>>();
    wsplit_build<<<(NGATE * DLAT) / 256, 256>>>(Wf, Wi, Wo, Wc);

    dim3 gridA(NGATE / A_BN, (SEQ * BATCH) / A_BM);
    input_gemm<<<gridA, 256>>>(x, Wf, Wi, Wo, Wc, bf, bi, bo, bc);

    for (int t = 0; t < SEQ; t++) {
        lstm_step_mma<<<128, 256, DSMEM_BYTES>>>(t, out);
    }
}

// round 6
// speedup vs baseline: 3.2148x; 1.3021x over previous
#include <cuda_runtime.h>
#include <cuda_bf16.h>
#include <math.h>
#include <stdint.h>

#define SEQ   512
#define BATCH 64
#define DIN   1024
#define DLAT  1024
#define DCAT  2048
#define NGATE 4096

// ---------------- device scratch ----------------
__device__ float g_gx[(size_t)SEQ * BATCH * NGATE];   // x-side gates (+bias)
__device__ __nv_bfloat16 g_whi[(size_t)NGATE * DLAT]; // wrow = j*4+gate, k-major
__device__ __nv_bfloat16 g_wlo[(size_t)NGATE * DLAT];
__device__ __nv_bfloat16 g_hhi[2][BATCH * DLAT];      // double-buffered split h
__device__ __nv_bfloat16 g_hlo[2][BATCH * DLAT];
__device__ unsigned g_bar_cnt;
__device__ unsigned g_bar_epoch;

__device__ __forceinline__ float sigmoidf_(float x) { return 1.0f / (1.0f + __expf(-x)); }

__device__ __forceinline__ uint32_t smem_u32(const void* p) {
    uint32_t a;
    asm("{ .reg .u64 t; cvta.to.shared.u64 t, %1; cvt.u32.u64 %0, t; }" : "=r"(a) : "l"(p));
    return a;
}

// ---------------------------------------------------------------
__global__ void init_state() {
    int i = blockIdx.x * blockDim.x + threadIdx.x;
    if (i < BATCH * DLAT) {
        g_hhi[0][i] = __float2bfloat16(0.0f);
        g_hlo[0][i] = __float2bfloat16(0.0f);
    }
    if (i == 0) { g_bar_cnt = 0; g_bar_epoch = 0; }
}

__global__ void wsplit_build(const float* __restrict__ Wf, const float* __restrict__ Wi,
                             const float* __restrict__ Wo, const float* __restrict__ Wc) {
    int idx = blockIdx.x * blockDim.x + threadIdx.x;   // 4096*1024
    int wrow = idx >> 10, k = idx & 1023;
    int j = wrow >> 2, gate = wrow & 3;
    const float* W = (gate == 0) ? Wf : (gate == 1) ? Wi : (gate == 2) ? Wo : Wc;
    float v = W[(size_t)j * DCAT + k];
    __nv_bfloat16 hi = __float2bfloat16(v);
    __nv_bfloat16 lo = __float2bfloat16(v - __bfloat162float(hi));
    g_whi[(size_t)wrow * DLAT + k] = hi;
    g_wlo[(size_t)wrow * DLAT + k] = lo;
}

// ---------------------------------------------------------------
// Phase A (unchanged): gx = x @ Wx^T + b, fp32 f32x2 SIMT
// ---------------------------------------------------------------
__device__ __forceinline__ unsigned long long pack2(float lo, float hi) {
    unsigned long long r;
    asm("mov.b64 %0, {%1, %2};" : "=l"(r) : "f"(lo), "f"(hi));
    return r;
}
__device__ __forceinline__ void unpack2(unsigned long long v, float& lo, float& hi) {
    asm("mov.b64 {%0, %1}, %2;" : "=f"(lo), "=f"(hi) : "l"(v));
}
__device__ __forceinline__ unsigned long long fma2(unsigned long long a,
                                                   unsigned long long b,
                                                   unsigned long long c) {
    unsigned long long d;
    asm("fma.rn.f32x2 %0, %1, %2, %3;" : "=l"(d) : "l"(a), "l"(b), "l"(c));
    return d;
}

#define A_BM 128
#define A_BN 64
#define A_BK 16

__global__ void __launch_bounds__(256) input_gemm(
    const float* __restrict__ x,
    const float* __restrict__ Wf, const float* __restrict__ Wi,
    const float* __restrict__ Wo, const float* __restrict__ Wc,
    const float* __restrict__ bf, const float* __restrict__ bi,
    const float* __restrict__ bo, const float* __restrict__ bc)
{
    __shared__ __align__(16) float As[A_BK][132];
    __shared__ __align__(16) float Bs[A_BK][68];

    const int tid = threadIdx.x;
    const int n0g = blockIdx.x * A_BN;
    const int gate = n0g >> 10;
    const int j0   = n0g & 1023;
    const float* W    = (gate == 0) ? Wf : (gate == 1) ? Wi : (gate == 2) ? Wo : Wc;
    const float* bias = (gate == 0) ? bf : (gate == 1) ? bi : (gate == 2) ? bo : bc;
    const int r0 = blockIdx.y * A_BM;

    const int nt = tid & 15, mt = tid >> 4;
    const int m0 = mt * 8, n0 = nt * 4;

    unsigned long long acc[4][4];
    #pragma unroll
    for (int i = 0; i < 4; i++)
        #pragma unroll
        for (int j = 0; j < 4; j++) acc[i][j] = 0ull;

    for (int k0 = 0; k0 < DIN; k0 += A_BK) {
        #pragma unroll
        for (int i = 0; i < 2; i++) {
            int idx = tid + i * 256;
            int m = idx >> 2, q = (idx & 3) * 4;
            float4 v = *(const float4*)&x[(size_t)(r0 + m) * DIN + k0 + q];
            As[q + 0][m] = v.x; As[q + 1][m] = v.y;
            As[q + 2][m] = v.z; As[q + 3][m] = v.w;
        }
        {
            int n = tid >> 2, q = (tid & 3) * 4;
            float4 v = *(const float4*)&W[(size_t)(j0 + n) * DCAT + DIN + k0 + q];
            Bs[q + 0][n] = v.x; Bs[q + 1][n] = v.y;
            Bs[q + 2][n] = v.z; Bs[q + 3][n] = v.w;
        }
        __syncthreads();

        #pragma unroll
        for (int k = 0; k < A_BK; k++) {
            ulonglong2 a01 = *(const ulonglong2*)&As[k][m0];
            ulonglong2 a23 = *(const ulonglong2*)&As[k][m0 + 4];
            float4 bv = *(const float4*)&Bs[k][n0];
            unsigned long long bd0 = pack2(bv.x, bv.x);
            unsigned long long bd1 = pack2(bv.y, bv.y);
            unsigned long long bd2 = pack2(bv.z, bv.z);
            unsigned long long bd3 = pack2(bv.w, bv.w);
            acc[0][0] = fma2(a01.x, bd0, acc[0][0]);
            acc[0][1] = fma2(a01.y, bd0, acc[0][1]);
            acc[0][2] = fma2(a23.x, bd0, acc[0][2]);
            acc[0][3] = fma2(a23.y, bd0, acc[0][3]);
            acc[1][0] = fma2(a01.x, bd1, acc[1][0]);
            acc[1][1] = fma2(a01.y, bd1, acc[1][1]);
            acc[1][2] = fma2(a23.x, bd1, acc[1][2]);
            acc[1][3] = fma2(a23.y, bd1, acc[1][3]);
            acc[2][0] = fma2(a01.x, bd2, acc[2][0]);
            acc[2][1] = fma2(a01.y, bd2, acc[2][1]);
            acc[2][2] = fma2(a23.x, bd2, acc[2][2]);
            acc[2][3] = fma2(a23.y, bd2, acc[2][3]);
            acc[3][0] = fma2(a01.x, bd3, acc[3][0]);
            acc[3][1] = fma2(a01.y, bd3, acc[3][1]);
            acc[3][2] = fma2(a23.x, bd3, acc[3][2]);
            acc[3][3] = fma2(a23.y, bd3, acc[3][3]);
        }
        __syncthreads();
    }

    float b0 = bias[j0 + n0 + 0], b1 = bias[j0 + n0 + 1];
    float b2 = bias[j0 + n0 + 2], b3 = bias[j0 + n0 + 3];
    #pragma unroll
    for (int mp = 0; mp < 4; mp++) {
        float v0l, v0h, v1l, v1h, v2l, v2h, v3l, v3h;
        unpack2(acc[0][mp], v0l, v0h);
        unpack2(acc[1][mp], v1l, v1h);
        unpack2(acc[2][mp], v2l, v2h);
        unpack2(acc[3][mp], v3l, v3h);
        int mA = r0 + m0 + 2 * mp;
        float4 lo = make_float4(v0l + b0, v1l + b1, v2l + b2, v3l + b3);
        float4 hi = make_float4(v0h + b0, v1h + b1, v2h + b2, v3h + b3);
        *(float4*)&g_gx[(size_t)mA * NGATE + n0g + n0]       = lo;
        *(float4*)&g_gx[(size_t)(mA + 1) * NGATE + n0g + n0] = hi;
    }
}

// ---------------------------------------------------------------
// Phase B: PERSISTENT weight-resident HMMA kernel.
// 128 blocks x 256 thr, 1 CTA/SM, all co-resident. Block owns 32 gate-rows
// (8 latents x 4 gates) for all 512 steps. W slice (hi+lo) lives in smem.
// Per step: stream split h (4-deep cp.async) + gx stage, 3-combo bf16 MMA,
// fused epilogue with cell state in registers, epoch grid-barrier.
// ---------------------------------------------------------------
// smem map (bytes from dynamic base):
//   W:  [split][32 rows][1032 bf16]  row stride 2064, split stride 66048, tot 132096
//   B:  4 bufs x [split][64 rows][72 bf16] = 4 x 18432 = 73728   @ 132096
//   gx: [64 m][36 floats]            = 9216                       @ 205824
#define WOFF_SPL  66048
#define WROW      2064
#define BBASE     132096
#define BBUF      18432
#define BSPL      9216
#define GXBASE    205824
#define DSMEM_BYTES 215040

#define CP16(dst, src) \
    asm volatile("cp.async.cg.shared.global [%0], [%1], 16;" :: "r"(dst), "l"(src))
#define CP_COMMIT() asm volatile("cp.async.commit_group;")
#define CP_WAIT(N)  asm volatile("cp.async.wait_group %0;" :: "n"(N))

__device__ __forceinline__ void mma_bf16(float c[4], uint32_t a0, uint32_t a1,
                                         uint32_t a2, uint32_t a3,
                                         uint32_t b0, uint32_t b1) {
    asm volatile("mma.sync.aligned.m16n8k16.row.col.f32.bf16.bf16.f32 "
        "{%0,%1,%2,%3}, {%4,%5,%6,%7}, {%8,%9}, {%0,%1,%2,%3};"
        : "+f"(c[0]), "+f"(c[1]), "+f"(c[2]), "+f"(c[3])
        : "r"(a0), "r"(a1), "r"(a2), "r"(a3), "r"(b0), "r"(b1));
}

__device__ __forceinline__ unsigned ld_vol(const unsigned* p) {
    unsigned v;
    asm volatile("ld.volatile.global.u32 %0, [%1];" : "=r"(v) : "l"(p));
    return v;
}

__global__ void __launch_bounds__(256) lstm_persistent(float* __restrict__ out)
{
    extern __shared__ __align__(16) uint8_t dsm[];
    const uint32_t sb = smem_u32(dsm);

    const int tid  = threadIdx.x;
    const int lane = tid & 31;
    const int wid  = tid >> 5;
    const int wm   = wid & 1;          // m-tile (16 gate-rows)
    const int wn   = wid >> 1;         // batch group (16)
    const int n0   = wn * 16;
    const int gid  = lane >> 2;
    const int tig  = lane & 3;

    const int r0 = blockIdx.x * 32;    // wrow base
    const int jb = blockIdx.x * 8;     // latent base

    // ---- load resident W slice (hi+lo) into smem ----
    #pragma unroll
    for (int i = 0; i < 32; i++) {
        int e = tid + i * 256;                   // 8192 x 16B
        int s = e >> 12, rem = e & 4095;
        int row = rem >> 7, seg = rem & 127;
        const __nv_bfloat16* src = (s ? g_wlo : g_whi)
            + (size_t)(r0 + row) * DLAT + seg * 8;
        CP16(sb + s * WOFF_SPL + row * WROW + seg * 16, src);
    }
    CP_COMMIT();
    CP_WAIT(0);
    __syncthreads();

    // cell state in registers (fixed (m, jl) ownership per thread)
    float creg[2] = {0.0f, 0.0f};
    const int q0  = tid * 2;
    const int em  = q0 >> 3;           // batch row (same for both pairs)
    const int ejl = q0 & 7;            // latent pair base (ejl, ejl+1)

    for (int t = 0; t < SEQ; t++) {
        // ---- grid barrier: all h(t) writes visible ----
        if (t > 0) {
            if (tid == 0) {
                if (atomicAdd(&g_bar_cnt, 1) == 127) {
                    g_bar_cnt = 0;
                    __threadfence();
                    atomicExch(&g_bar_epoch, (unsigned)t);
                } else {
                    while (ld_vol(&g_bar_epoch) < (unsigned)t) {}
                }
                __threadfence();
            }
            __syncthreads();
        }

        const int rb = t & 1;
        const __nv_bfloat16* hhi = g_hhi[rb];
        const __nv_bfloat16* hlo = g_hlo[rb];

        // ---- fill B chunk c into buf c&3 ----
        #define FILL_B(C) do {                                                   \
            _Pragma("unroll")                                                    \
            for (int i = 0; i < 4; i++) {                                        \
                int e = tid + i * 256;                                           \
                int s = e >> 9, row = (e >> 3) & 63, seg = e & 7;                \
                const __nv_bfloat16* src = (s ? hlo : hhi)                       \
                    + (size_t)row * DLAT + (C) * 64 + seg * 8;                   \
                CP16(sb + BBASE + ((C) & 3) * BBUF + s * BSPL + row * 144 + seg * 16, src); \
            }                                                                    \
            CP_COMMIT();                                                         \
        } while (0)

        // gx stage rides with chunk 0's commit group
        {
            const float* gxt = g_gx + (size_t)t * BATCH * NGATE;
            #pragma unroll
            for (int i = 0; i < 2; i++) {
                int e = tid + i * 256;
                int m = e >> 3, g = (e >> 1) & 3, half = e & 1;
                const float* src = gxt + (size_t)m * NGATE + g * 1024 + jb + half * 4;
                CP16(sb + GXBASE + m * 144 + g * 32 + half * 16, src);
            }
            #pragma unroll
            for (int i = 0; i < 4; i++) {
                int e = tid + i * 256;
                int s = e >> 9, row = (e >> 3) & 63, seg = e & 7;
                const __nv_bfloat16* src = (s ? hlo : hhi)
                    + (size_t)row * DLAT + seg * 8;
                CP16(sb + BBASE + s * BSPL + row * 144 + seg * 16, src);
            }
            CP_COMMIT();
        }
        FILL_B(1);
        FILL_B(2);
        FILL_B(3);

        float aHH[2][4], aHL[2][4], aLH[2][4];
        #pragma unroll
        for (int nt2 = 0; nt2 < 2; nt2++)
            #pragma unroll
            for (int i = 0; i < 4; i++) { aHH[nt2][i] = 0.f; aHL[nt2][i] = 0.f; aLH[nt2][i] = 0.f; }

        #pragma unroll 1
        for (int c = 0; c < 16; c++) {
            if (15 - c >= 3) CP_WAIT(3);
            else if (15 - c == 2) CP_WAIT(2);
            else if (15 - c == 1) CP_WAIT(1);
            else CP_WAIT(0);
            __syncthreads();

            const uint32_t bB = sb + BBASE + (c & 3) * BBUF;
            const int kbase = c * 64;

            #pragma unroll
            for (int q = 0; q < 4; q++) {
                const uint32_t ka = (uint32_t)(kbase + q * 16 + tig * 2) * 2;
                const uint32_t ar0 = sb + (wm * 16 + gid) * WROW + ka;
                const uint32_t ar1 = ar0 + 8 * WROW;
                uint32_t ah0, ah1, ah2, ah3, al0, al1, al2, al3;
                asm volatile("ld.shared.b32 %0, [%1];" : "=r"(ah0) : "r"(ar0));
                asm volatile("ld.shared.b32 %0, [%1];" : "=r"(ah1) : "r"(ar1));
                asm volatile("ld.shared.b32 %0, [%1];" : "=r"(ah2) : "r"(ar0 + 16));
                asm volatile("ld.shared.b32 %0, [%1];" : "=r"(ah3) : "r"(ar1 + 16));
                asm volatile("ld.shared.b32 %0, [%1];" : "=r"(al0) : "r"(ar0 + WOFF_SPL));
                asm volatile("ld.shared.b32 %0, [%1];" : "=r"(al1) : "r"(ar1 + WOFF_SPL));
                asm volatile("ld.shared.b32 %0, [%1];" : "=r"(al2) : "r"(ar0 + 16 + WOFF_SPL));
                asm volatile("ld.shared.b32 %0, [%1];" : "=r"(al3) : "r"(ar1 + 16 + WOFF_SPL));
                #pragma unroll
                for (int nt2 = 0; nt2 < 2; nt2++) {
                    const uint32_t br = bB + (n0 + nt2 * 8 + gid) * 144 + (uint32_t)(q * 16 + tig * 2) * 2;
                    uint32_t bh0, bh1, bl0, bl1;
                    asm volatile("ld.shared.b32 %0, [%1];" : "=r"(bh0) : "r"(br));
                    asm volatile("ld.shared.b32 %0, [%1];" : "=r"(bh1) : "r"(br + 16));
                    asm volatile("ld.shared.b32 %0, [%1];" : "=r"(bl0) : "r"(br + BSPL));
                    asm volatile("ld.shared.b32 %0, [%1];" : "=r"(bl1) : "r"(br + BSPL + 16));
                    mma_bf16(aHH[nt2], ah0, ah1, ah2, ah3, bh0, bh1);
                    mma_bf16(aHL[nt2], ah0, ah1, ah2, ah3, bl0, bl1);
                    mma_bf16(aLH[nt2], al0, al1, al2, al3, bh0, bh1);
                }
            }
            __syncthreads();
            if (c + 4 < 16) FILL_B(c + 4);
        }

        // ---- exchange via smem (reuse B buffers): ex[32 rows][stride 65] ----
        float* ex = (float*)(dsm + BBASE);
        #pragma unroll
        for (int nt2 = 0; nt2 < 2; nt2++) {
            int R0 = wm * 16 + gid, C0 = n0 + nt2 * 8 + tig * 2;
            float v0 = aHH[nt2][0] + aHL[nt2][0] + aLH[nt2][0];
            float v1 = aHH[nt2][1] + aHL[nt2][1] + aLH[nt2][1];
            float v2 = aHH[nt2][2] + aHL[nt2][2] + aLH[nt2][2];
            float v3 = aHH[nt2][3] + aHL[nt2][3] + aLH[nt2][3];
            ex[R0 * 65 + C0]           = v0;
            ex[R0 * 65 + C0 + 1]       = v1;
            ex[(R0 + 8) * 65 + C0]     = v2;
            ex[(R0 + 8) * 65 + C0 + 1] = v3;
        }
        __syncthreads();

        // ---- fused epilogue: thread owns (em, ejl) and (em, ejl+1) ----
        const float* gxs = (const float*)(dsm + GXBASE);
        __nv_bfloat16* hwh = g_hhi[rb ^ 1];
        __nv_bfloat16* hwl = g_hlo[rb ^ 1];
        #pragma unroll
        for (int p = 0; p < 2; p++) {
            const int jl = ejl + p;
            const int j  = jb + jl;
            float sf = ex[(jl * 4 + 0) * 65 + em];
            float si = ex[(jl * 4 + 1) * 65 + em];
            float so = ex[(jl * 4 + 2) * 65 + em];
            float sg = ex[(jl * 4 + 3) * 65 + em];
            float vf = sigmoidf_(sf + gxs[em * 36 + 0 * 8 + jl]);
            float vi = sigmoidf_(si + gxs[em * 36 + 1 * 8 + jl]);
            float vo = sigmoidf_(so + gxs[em * 36 + 2 * 8 + jl]);
            float vg = tanhf(sg + gxs[em * 36 + 3 * 8 + jl]);
            float cc = vf * creg[p] + vi * vg;
            creg[p] = cc;
            float h = vo * tanhf(cc);
            out[((size_t)t * BATCH + em) * DLAT + j] = h;
            __nv_bfloat16 hh = __float2bfloat16(h);
            __nv_bfloat16 hl = __float2bfloat16(h - __bfloat162float(hh));
            hwh[(size_t)em * DLAT + j] = hh;
            hwl[(size_t)em * DLAT + j] = hl;
        }
        __threadfence();
        __syncthreads();
    }
}

// ---------------------------------------------------------------
extern "C" void kernel_launch(void* const* d_in, const int* in_sizes, int n_in,
                              void* d_out, int out_size)
{
    const float* x  = (const float*)d_in[0];
    const float* Wf = (const float*)d_in[1];
    const float* bf = (const float*)d_in[2];
    const float* Wi = (const float*)d_in[3];
    const float* bi = (const float*)d_in[4];
    const float* Wo = (const float*)d_in[5];
    const float* bo = (const float*)d_in[6];
    const float* Wc = (const float*)d_in[7];
    const float* bc = (const float*)d_in[8];
    float* out = (float*)d_out;

    cudaFuncSetAttribute(lstm_persistent, cudaFuncAttributeMaxDynamicSharedMemorySize,
                         DSMEM_BYTES);

    init_state<<<256, 256>>>();
    wsplit_build<<<(NGATE * DLAT) / 256, 256>>>(Wf, Wi, Wo, Wc);

    dim3 gridA(NGATE / A_BN, (SEQ * BATCH) / A_BM);
    input_gemm<<<gridA, 256>>>(x, Wf, Wi, Wo, Wc, bf, bi, bo, bc);

    lstm_persistent<<<128, 256, DSMEM_BYTES>>>(out);
}

// round 7
// speedup vs baseline: 4.3281x; 1.3463x over previous
#include <cuda_runtime.h>
#include <cuda_bf16.h>
#include <math.h>
#include <stdint.h>

#define SEQ   512
#define BATCH 64
#define DIN   1024
#define DLAT  1024
#define DCAT  2048
#define NGATE 4096

// ---------------- device scratch ----------------
__device__ float g_gx[(size_t)SEQ * BATCH * NGATE];   // x-side gates (+bias)
__device__ __nv_bfloat16 g_whi[(size_t)NGATE * DLAT]; // recurrent W, wrow = j*4+gate
__device__ __nv_bfloat16 g_wlo[(size_t)NGATE * DLAT];
__device__ __nv_bfloat16 g_wxhi[(size_t)NGATE * DIN]; // x-part W, n = gate*1024+j
__device__ __nv_bfloat16 g_wxlo[(size_t)NGATE * DIN];
__device__ __nv_bfloat16 g_xhi[(size_t)SEQ * BATCH * DIN];
__device__ __nv_bfloat16 g_xlo[(size_t)SEQ * BATCH * DIN];
__device__ __nv_bfloat16 g_hhi[2][BATCH * DLAT];      // double-buffered split h
__device__ __nv_bfloat16 g_hlo[2][BATCH * DLAT];
__device__ unsigned g_bar_cnt;
__device__ unsigned g_bar_epoch;

__device__ __forceinline__ float sigmoidf_(float x) { return 1.0f / (1.0f + __expf(-x)); }

__device__ __forceinline__ uint32_t smem_u32(const void* p) {
    uint32_t a;
    asm("{ .reg .u64 t; cvta.to.shared.u64 t, %1; cvt.u32.u64 %0, t; }" : "=r"(a) : "l"(p));
    return a;
}

#define CP16(dst, src) \
    asm volatile("cp.async.cg.shared.global [%0], [%1], 16;" :: "r"(dst), "l"(src))
#define CP_COMMIT() asm volatile("cp.async.commit_group;")
#define CP_WAIT(N)  asm volatile("cp.async.wait_group %0;" :: "n"(N))

__device__ __forceinline__ void mma_bf16(float c[4], uint32_t a0, uint32_t a1,
                                         uint32_t a2, uint32_t a3,
                                         uint32_t b0, uint32_t b1) {
    asm volatile("mma.sync.aligned.m16n8k16.row.col.f32.bf16.bf16.f32 "
        "{%0,%1,%2,%3}, {%4,%5,%6,%7}, {%8,%9}, {%0,%1,%2,%3};"
        : "+f"(c[0]), "+f"(c[1]), "+f"(c[2]), "+f"(c[3])
        : "r"(a0), "r"(a1), "r"(a2), "r"(a3), "r"(b0), "r"(b1));
}

__device__ __forceinline__ uint32_t lds32(uint32_t addr) {
    uint32_t v;
    asm volatile("ld.shared.b32 %0, [%1];" : "=r"(v) : "r"(addr));
    return v;
}

__device__ __forceinline__ unsigned ld_vol(const unsigned* p) {
    unsigned v;
    asm volatile("ld.volatile.global.u32 %0, [%1];" : "=r"(v) : "l"(p));
    return v;
}

// ---------------------------------------------------------------
__global__ void init_state() {
    int i = blockIdx.x * blockDim.x + threadIdx.x;
    if (i < BATCH * DLAT) {
        g_hhi[0][i] = __float2bfloat16(0.0f);
        g_hlo[0][i] = __float2bfloat16(0.0f);
    }
    if (i == 0) { g_bar_cnt = 0; g_bar_epoch = 0; }
}

// Split ALL of W into bf16 hi/lo images: recurrent part (k<1024, wrow-major)
// and x part (k>=1024, gate-major n).
__global__ void wsplit_build(const float* __restrict__ Wf, const float* __restrict__ Wi,
                             const float* __restrict__ Wo, const float* __restrict__ Wc) {
    int idx = blockIdx.x * blockDim.x + threadIdx.x;   // over 4096*2048
    int n = idx >> 11, k2 = idx & 2047;
    int gate = n >> 10, j = n & 1023;
    const float* W = (gate == 0) ? Wf : (gate == 1) ? Wi : (gate == 2) ? Wo : Wc;
    float v = W[(size_t)j * DCAT + k2];
    __nv_bfloat16 hi = __float2bfloat16(v);
    __nv_bfloat16 lo = __float2bfloat16(v - __bfloat162float(hi));
    if (k2 < 1024) {
        int wrow = j * 4 + gate;
        g_whi[(size_t)wrow * DLAT + k2] = hi;
        g_wlo[(size_t)wrow * DLAT + k2] = lo;
    } else {
        g_wxhi[(size_t)n * DIN + (k2 - 1024)] = hi;
        g_wxlo[(size_t)n * DIN + (k2 - 1024)] = lo;
    }
}

// Split x into bf16 hi/lo
__global__ void xsplit_build(const float* __restrict__ x) {
    size_t i4 = (size_t)blockIdx.x * blockDim.x + threadIdx.x;  // over total/4
    float4 v = ((const float4*)x)[i4];
    size_t b = i4 * 4;
    float vv[4] = {v.x, v.y, v.z, v.w};
    #pragma unroll
    for (int p = 0; p < 4; p++) {
        __nv_bfloat16 hi = __float2bfloat16(vv[p]);
        __nv_bfloat16 lo = __float2bfloat16(vv[p] - __bfloat162float(hi));
        g_xhi[b + p] = hi;
        g_xlo[b + p] = lo;
    }
}

// ---------------------------------------------------------------
// Phase A: gx[m][n] = x[m] . Wx[n] + bias[n], split-bf16 3-combo HMMA.
// M=32768 (MMA-M, x rows), N=4096 (MMA-N, gate cols), K=1024.
// Block 128m x 128n x BK64, 256 thr (8 warps = 2m x 4n), warp 64m x 32n.
// smem/buffer: [Ahi][Alo][Bhi][Blo], row stride 144B, 2 buffers.
// ---------------------------------------------------------------
#define IA_SPL   18432            // 128 rows * 144B
#define IA_BOFF  36864            // B starts after A hi+lo
#define IA_BUF   73728
#define IA_DSMEM 147456

__global__ void __launch_bounds__(256) input_hmma(
    const float* __restrict__ bf, const float* __restrict__ bi,
    const float* __restrict__ bo, const float* __restrict__ bc)
{
    extern __shared__ __align__(16) uint8_t dsm[];
    __shared__ float sbias[128];
    const uint32_t sb = smem_u32(dsm);

    const int tid  = threadIdx.x;
    const int lane = tid & 31;
    const int wid  = tid >> 5;
    const int wm   = wid & 1;           // m half (64 rows)
    const int wn   = wid >> 1;          // n quarter (32 cols)
    const int gid  = lane >> 2;
    const int tig  = lane & 3;

    const int n0g = blockIdx.x * 128;
    const int m0g = blockIdx.y * 128;

    if (tid < 128) {
        int gate = n0g >> 10;
        const float* bsrc = (gate == 0) ? bf : (gate == 1) ? bi : (gate == 2) ? bo : bc;
        sbias[tid] = bsrc[(n0g & 1023) + tid];
    }

    // fill buffer BUF with k-chunk C (64 k): 16 CP16/thread
    #define IA_FILL(BUF, C) do {                                                 \
        _Pragma("unroll")                                                        \
        for (int i = 0; i < 16; i++) {                                           \
            int e = tid + i * 256;                                               \
            int part = e >> 11, rem = e & 2047;                                  \
            int s = rem >> 10, r2 = rem & 1023;                                  \
            int row = r2 >> 3, seg = r2 & 7;                                     \
            const __nv_bfloat16* src;                                            \
            if (part == 0)                                                       \
                src = (s ? g_xlo : g_xhi) + (size_t)(m0g + row) * DIN + (C) * 64 + seg * 8; \
            else                                                                 \
                src = (s ? g_wxlo : g_wxhi) + (size_t)(n0g + row) * DIN + (C) * 64 + seg * 8; \
            CP16(sb + (BUF) * IA_BUF + part * IA_BOFF + s * IA_SPL + row * 144 + seg * 16, src); \
        }                                                                        \
        CP_COMMIT();                                                             \
    } while (0)

    float acc[4][4][4];
    #pragma unroll
    for (int t = 0; t < 4; t++)
        #pragma unroll
        for (int u = 0; u < 4; u++)
            #pragma unroll
            for (int i = 0; i < 4; i++) acc[t][u][i] = 0.0f;

    IA_FILL(0, 0);
    IA_FILL(1, 1);

    #pragma unroll 1
    for (int c = 0; c < 16; c++) {
        if (c + 2 < 16) CP_WAIT(1); else CP_WAIT(0);
        __syncthreads();
        const uint32_t base = sb + (c & 1) * IA_BUF;

        #pragma unroll
        for (int q = 0; q < 4; q++) {
            const uint32_t kk2 = (uint32_t)(q * 16 + tig * 2) * 2;
            uint32_t aH[4][4], aL[4][4];
            #pragma unroll
            for (int t = 0; t < 4; t++) {
                uint32_t ar = base + (wm * 64 + t * 16 + gid) * 144 + kk2;
                aH[t][0] = lds32(ar);
                aH[t][1] = lds32(ar + 8 * 144);
                aH[t][2] = lds32(ar + 16);
                aH[t][3] = lds32(ar + 8 * 144 + 16);
                aL[t][0] = lds32(ar + IA_SPL);
                aL[t][1] = lds32(ar + IA_SPL + 8 * 144);
                aL[t][2] = lds32(ar + IA_SPL + 16);
                aL[t][3] = lds32(ar + IA_SPL + 8 * 144 + 16);
            }
            #pragma unroll
            for (int u = 0; u < 4; u++) {
                uint32_t br = base + IA_BOFF + (wn * 32 + u * 8 + gid) * 144 + kk2;
                uint32_t bh0 = lds32(br);
                uint32_t bh1 = lds32(br + 16);
                uint32_t bl0 = lds32(br + IA_SPL);
                uint32_t bl1 = lds32(br + IA_SPL + 16);
                #pragma unroll
                for (int t = 0; t < 4; t++) {
                    mma_bf16(acc[t][u], aH[t][0], aH[t][1], aH[t][2], aH[t][3], bh0, bh1);
                    mma_bf16(acc[t][u], aH[t][0], aH[t][1], aH[t][2], aH[t][3], bl0, bl1);
                    mma_bf16(acc[t][u], aL[t][0], aL[t][1], aL[t][2], aL[t][3], bh0, bh1);
                }
            }
        }
        __syncthreads();
        if (c + 2 < 16) IA_FILL(c & 1, c + 2);
    }

    // epilogue: bias add + v2 stores
    #pragma unroll
    for (int t = 0; t < 4; t++) {
        const int row = m0g + wm * 64 + t * 16 + gid;
        #pragma unroll
        for (int u = 0; u < 4; u++) {
            const int cl = wn * 32 + u * 8 + tig * 2;
            const int col = n0g + cl;
            float b0 = sbias[cl], b1 = sbias[cl + 1];
            float2 v01 = make_float2(acc[t][u][0] + b0, acc[t][u][1] + b1);
            float2 v23 = make_float2(acc[t][u][2] + b0, acc[t][u][3] + b1);
            *(float2*)&g_gx[(size_t)row * NGATE + col]       = v01;
            *(float2*)&g_gx[(size_t)(row + 8) * NGATE + col] = v23;
        }
    }
}

// ---------------------------------------------------------------
// Phase B: PERSISTENT weight-resident HMMA kernel.
// 128 blocks x 256 thr, all co-resident. W slice (hi+lo) resident in smem.
// Per step: 8 K-chunks of 128, 2-buffer cp.async; 3-combo MMA; fused
// epilogue with cell state in registers; tid0-fence grid barrier.
// ---------------------------------------------------------------
#define WROW      2064
#define WOFF_SPL  66048
#define BBASE     132096
#define BROW      272
#define BSPL      17408           // 64 * 272
#define BBUF      34816
#define GXBASE    201728          // BBASE + 2*BBUF
#define DSMEM_BYTES 210944        // GXBASE + 64*144

__global__ void __launch_bounds__(256) lstm_persistent(float* __restrict__ out)
{
    extern __shared__ __align__(16) uint8_t dsm[];
    const uint32_t sb = smem_u32(dsm);

    const int tid  = threadIdx.x;
    const int lane = tid & 31;
    const int wid  = tid >> 5;
    const int wm   = wid & 1;          // m-tile (16 gate-rows)
    const int wn   = wid >> 1;         // batch group (16)
    const int n0   = wn * 16;
    const int gid  = lane >> 2;
    const int tig  = lane & 3;

    const int r0 = blockIdx.x * 32;    // wrow base
    const int jb = blockIdx.x * 8;     // latent base

    // ---- load resident W slice (hi+lo) ----
    #pragma unroll
    for (int i = 0; i < 32; i++) {
        int e = tid + i * 256;
        int s = e >> 12, rem = e & 4095;
        int row = rem >> 7, seg = rem & 127;
        const __nv_bfloat16* src = (s ? g_wlo : g_whi)
            + (size_t)(r0 + row) * DLAT + seg * 8;
        CP16(sb + s * WOFF_SPL + row * WROW + seg * 16, src);
    }
    CP_COMMIT();
    CP_WAIT(0);
    __syncthreads();

    float creg[2] = {0.0f, 0.0f};
    const int q0  = tid * 2;
    const int em  = q0 >> 3;           // batch row
    const int ejl = q0 & 7;            // latent pair base

    for (int t = 0; t < SEQ; t++) {
        // ---- grid barrier (tid0 fence + arrive + spin) ----
        if (t > 0) {
            if (tid == 0) {
                __threadfence();
                if (atomicAdd(&g_bar_cnt, 1) == 127) {
                    g_bar_cnt = 0;
                    atomicExch(&g_bar_epoch, (unsigned)t);
                } else {
                    while (ld_vol(&g_bar_epoch) < (unsigned)t) {}
                }
                __threadfence();
            }
            __syncthreads();
        }

        const int rb = t & 1;
        const __nv_bfloat16* hhi = g_hhi[rb];
        const __nv_bfloat16* hlo = g_hlo[rb];

        // fill B chunk C (128 k) into buf C&1: 8 CP16/thread
        #define FILL_B(C) do {                                                   \
            _Pragma("unroll")                                                    \
            for (int i = 0; i < 8; i++) {                                        \
                int e = tid + i * 256;                                           \
                int s = e >> 10, rem = e & 1023;                                 \
                int row = rem >> 4, seg = rem & 15;                              \
                const __nv_bfloat16* src = (s ? hlo : hhi)                       \
                    + (size_t)row * DLAT + (C) * 128 + seg * 8;                  \
                CP16(sb + BBASE + ((C) & 1) * BBUF + s * BSPL + row * BROW + seg * 16, src); \
            }                                                                    \
            CP_COMMIT();                                                         \
        } while (0)

        // gx stage rides with chunk 0's group
        {
            const float* gxt = g_gx + (size_t)t * BATCH * NGATE;
            #pragma unroll
            for (int i = 0; i < 2; i++) {
                int e = tid + i * 256;
                int m = e >> 3, g = (e >> 1) & 3, half = e & 1;
                const float* src = gxt + (size_t)m * NGATE + g * 1024 + jb + half * 4;
                CP16(sb + GXBASE + m * 144 + g * 32 + half * 16, src);
            }
            #pragma unroll
            for (int i = 0; i < 8; i++) {
                int e = tid + i * 256;
                int s = e >> 10, rem = e & 1023;
                int row = rem >> 4, seg = rem & 15;
                const __nv_bfloat16* src = (s ? hlo : hhi)
                    + (size_t)row * DLAT + seg * 8;
                CP16(sb + BBASE + s * BSPL + row * BROW + seg * 16, src);
            }
            CP_COMMIT();
        }
        FILL_B(1);

        float aHH[2][4], aHL[2][4], aLH[2][4];
        #pragma unroll
        for (int nt2 = 0; nt2 < 2; nt2++)
            #pragma unroll
            for (int i = 0; i < 4; i++) { aHH[nt2][i] = 0.f; aHL[nt2][i] = 0.f; aLH[nt2][i] = 0.f; }

        #pragma unroll 1
        for (int c = 0; c < 8; c++) {
            if (c + 2 < 8) CP_WAIT(1); else CP_WAIT(0);
            __syncthreads();

            const uint32_t bB = sb + BBASE + (c & 1) * BBUF;
            const int kbase = c * 128;

            #pragma unroll
            for (int q = 0; q < 8; q++) {
                const uint32_t ka = (uint32_t)(q * 16 + tig * 2) * 2;
                const uint32_t ar0 = sb + (wm * 16 + gid) * WROW + (uint32_t)(kbase) * 2 + ka;
                const uint32_t ar1 = ar0 + 8 * WROW;
                uint32_t ah0 = lds32(ar0);
                uint32_t ah1 = lds32(ar1);
                uint32_t ah2 = lds32(ar0 + 16);
                uint32_t ah3 = lds32(ar1 + 16);
                uint32_t al0 = lds32(ar0 + WOFF_SPL);
                uint32_t al1 = lds32(ar1 + WOFF_SPL);
                uint32_t al2 = lds32(ar0 + 16 + WOFF_SPL);
                uint32_t al3 = lds32(ar1 + 16 + WOFF_SPL);
                #pragma unroll
                for (int nt2 = 0; nt2 < 2; nt2++) {
                    const uint32_t br = bB + (n0 + nt2 * 8 + gid) * BROW + ka;
                    uint32_t bh0 = lds32(br);
                    uint32_t bh1 = lds32(br + 16);
                    uint32_t bl0 = lds32(br + BSPL);
                    uint32_t bl1 = lds32(br + BSPL + 16);
                    mma_bf16(aHH[nt2], ah0, ah1, ah2, ah3, bh0, bh1);
                    mma_bf16(aHL[nt2], ah0, ah1, ah2, ah3, bl0, bl1);
                    mma_bf16(aLH[nt2], al0, al1, al2, al3, bh0, bh1);
                }
            }
            __syncthreads();
            if (c + 2 < 8) FILL_B(c + 2);
        }

        // ---- exchange via smem (reuse B buffers): ex[32 rows][stride 65] ----
        float* ex = (float*)(dsm + BBASE);
        #pragma unroll
        for (int nt2 = 0; nt2 < 2; nt2++) {
            int R0 = wm * 16 + gid, C0 = n0 + nt2 * 8 + tig * 2;
            ex[R0 * 65 + C0]           = aHH[nt2][0] + aHL[nt2][0] + aLH[nt2][0];
            ex[R0 * 65 + C0 + 1]       = aHH[nt2][1] + aHL[nt2][1] + aLH[nt2][1];
            ex[(R0 + 8) * 65 + C0]     = aHH[nt2][2] + aHL[nt2][2] + aLH[nt2][2];
            ex[(R0 + 8) * 65 + C0 + 1] = aHH[nt2][3] + aHL[nt2][3] + aLH[nt2][3];
        }
        __syncthreads();

        // ---- fused epilogue ----
        const float* gxs = (const float*)(dsm + GXBASE);
        __nv_bfloat16* hwh = g_hhi[rb ^ 1];
        __nv_bfloat16* hwl = g_hlo[rb ^ 1];
        #pragma unroll
        for (int p = 0; p < 2; p++) {
            const int jl = ejl + p;
            const int j  = jb + jl;
            float sf = ex[(jl * 4 + 0) * 65 + em];
            float si = ex[(jl * 4 + 1) * 65 + em];
            float so = ex[(jl * 4 + 2) * 65 + em];
            float sg = ex[(jl * 4 + 3) * 65 + em];
            float vf = sigmoidf_(sf + gxs[em * 36 + 0 * 8 + jl]);
            float vi = sigmoidf_(si + gxs[em * 36 + 1 * 8 + jl]);
            float vo = sigmoidf_(so + gxs[em * 36 + 2 * 8 + jl]);
            float vg = tanhf(sg + gxs[em * 36 + 3 * 8 + jl]);
            float cc = vf * creg[p] + vi * vg;
            creg[p] = cc;
            float h = vo * tanhf(cc);
            out[((size_t)t * BATCH + em) * DLAT + j] = h;
            __nv_bfloat16 hh = __float2bfloat16(h);
            __nv_bfloat16 hl = __float2bfloat16(h - __bfloat162float(hh));
            hwh[(size_t)em * DLAT + j] = hh;
            hwl[(size_t)em * DLAT + j] = hl;
        }
        __syncthreads();
    }
}

// ---------------------------------------------------------------
extern "C" void kernel_launch(void* const* d_in, const int* in_sizes, int n_in,
                              void* d_out, int out_size)
{
    const float* x  = (const float*)d_in[0];
    const float* Wf = (const float*)d_in[1];
    const float* bf = (const float*)d_in[2];
    const float* Wi = (const float*)d_in[3];
    const float* bi = (const float*)d_in[4];
    const float* Wo = (const float*)d_in[5];
    const float* bo = (const float*)d_in[6];
    const float* Wc = (const float*)d_in[7];
    const float* bc = (const float*)d_in[8];
    float* out = (float*)d_out;

    cudaFuncSetAttribute(input_hmma, cudaFuncAttributeMaxDynamicSharedMemorySize,
                         IA_DSMEM);
    cudaFuncSetAttribute(lstm_persistent, cudaFuncAttributeMaxDynamicSharedMemorySize,
                         DSMEM_BYTES);

    init_state<<<256, 256>>>();
    wsplit_build<<<(NGATE * DCAT) / 256, 256>>>(Wf, Wi, Wo, Wc);
    xsplit_build<<<(SEQ * BATCH * DIN) / (4 * 256), 256>>>(x);

    dim3 gridA(NGATE / 128, (SEQ * BATCH) / 128);   // (32, 256)
    input_hmma<<<gridA, 256, IA_DSMEM>>>(bf, bi, bo, bc);

    lstm_persistent<<<128, 256, DSMEM_BYTES>>>(out);
}

// round 8
// speedup vs baseline: 4.8243x; 1.1147x over previous
#include <cuda_runtime.h>
#include <cuda_bf16.h>
#include <cuda_fp16.h>
#include <math.h>
#include <stdint.h>

#define SEQ   512
#define BATCH 64
#define DIN   1024
#define DLAT  1024
#define DCAT  2048
#define NGATE 4096

// ---------------- device scratch ----------------
__device__ float g_gx[(size_t)SEQ * BATCH * NGATE];   // x-side gates (+bias)
__device__ __nv_bfloat16 g_whi[(size_t)NGATE * DLAT]; // recurrent W, wrow = j*4+gate
__device__ __nv_bfloat16 g_wlo[(size_t)NGATE * DLAT];
__device__ __half g_wx[(size_t)NGATE * DIN];          // x-part W, fp16 single
__device__ __half g_xh[(size_t)SEQ * BATCH * DIN];    // x fp16 hi
__device__ __half g_xl[(size_t)SEQ * BATCH * DIN];    // x fp16 lo
__device__ __nv_bfloat16 g_hhi[2][BATCH * DLAT];      // double-buffered split h
__device__ __nv_bfloat16 g_hlo[2][BATCH * DLAT];
__device__ unsigned g_flags[128];
__device__ unsigned g_epoch2;

__device__ __forceinline__ float sigmoidf_(float x) {
    return __fdividef(1.0f, 1.0f + __expf(-x));
}
__device__ __forceinline__ float tanhf_(float x) {
    float e = __expf(2.0f * x);
    return 1.0f - __fdividef(2.0f, e + 1.0f);
}

__device__ __forceinline__ uint32_t smem_u32(const void* p) {
    uint32_t a;
    asm("{ .reg .u64 t; cvta.to.shared.u64 t, %1; cvt.u32.u64 %0, t; }" : "=r"(a) : "l"(p));
    return a;
}

#define CP16(dst, src) \
    asm volatile("cp.async.cg.shared.global [%0], [%1], 16;" :: "r"(dst), "l"(src))
#define CP_COMMIT() asm volatile("cp.async.commit_group;")
#define CP_WAIT(N)  asm volatile("cp.async.wait_group %0;" :: "n"(N))

__device__ __forceinline__ void mma_bf16(float c[4], uint32_t a0, uint32_t a1,
                                         uint32_t a2, uint32_t a3,
                                         uint32_t b0, uint32_t b1) {
    asm volatile("mma.sync.aligned.m16n8k16.row.col.f32.bf16.bf16.f32 "
        "{%0,%1,%2,%3}, {%4,%5,%6,%7}, {%8,%9}, {%0,%1,%2,%3};"
        : "+f"(c[0]), "+f"(c[1]), "+f"(c[2]), "+f"(c[3])
        : "r"(a0), "r"(a1), "r"(a2), "r"(a3), "r"(b0), "r"(b1));
}
__device__ __forceinline__ void mma_f16(float c[4], uint32_t a0, uint32_t a1,
                                        uint32_t a2, uint32_t a3,
                                        uint32_t b0, uint32_t b1) {
    asm volatile("mma.sync.aligned.m16n8k16.row.col.f32.f16.f16.f32 "
        "{%0,%1,%2,%3}, {%4,%5,%6,%7}, {%8,%9}, {%0,%1,%2,%3};"
        : "+f"(c[0]), "+f"(c[1]), "+f"(c[2]), "+f"(c[3])
        : "r"(a0), "r"(a1), "r"(a2), "r"(a3), "r"(b0), "r"(b1));
}

__device__ __forceinline__ uint32_t lds32(uint32_t addr) {
    uint32_t v;
    asm volatile("ld.shared.b32 %0, [%1];" : "=r"(v) : "r"(addr));
    return v;
}
__device__ __forceinline__ unsigned ld_acq(const unsigned* p) {
    unsigned v;
    asm volatile("ld.acquire.gpu.global.u32 %0, [%1];" : "=r"(v) : "l"(p));
    return v;
}
__device__ __forceinline__ void st_rel(unsigned* p, unsigned v) {
    asm volatile("st.release.gpu.global.u32 [%0], %1;" :: "l"(p), "r"(v) : "memory");
}

// ---------------------------------------------------------------
__global__ void init_state() {
    int i = blockIdx.x * blockDim.x + threadIdx.x;
    if (i < BATCH * DLAT) {
        g_hhi[0][i] = __float2bfloat16(0.0f);
        g_hlo[0][i] = __float2bfloat16(0.0f);
    }
    if (i < 128) g_flags[i] = 0;
    if (i == 0) g_epoch2 = 0;
}

// Split W: recurrent part (k<1024) -> bf16 hi/lo pair; x part -> fp16 single.
__global__ void wsplit_build(const float* __restrict__ Wf, const float* __restrict__ Wi,
                             const float* __restrict__ Wo, const float* __restrict__ Wc) {
    int idx = blockIdx.x * blockDim.x + threadIdx.x;   // over 4096*2048
    int n = idx >> 11, k2 = idx & 2047;
    int gate = n >> 10, j = n & 1023;
    const float* W = (gate == 0) ? Wf : (gate == 1) ? Wi : (gate == 2) ? Wo : Wc;
    float v = W[(size_t)j * DCAT + k2];
    if (k2 < 1024) {
        __nv_bfloat16 hi = __float2bfloat16(v);
        __nv_bfloat16 lo = __float2bfloat16(v - __bfloat162float(hi));
        int wrow = j * 4 + gate;
        g_whi[(size_t)wrow * DLAT + k2] = hi;
        g_wlo[(size_t)wrow * DLAT + k2] = lo;
    } else {
        g_wx[(size_t)n * DIN + (k2 - 1024)] = __float2half(v);
    }
}

// Split x into fp16 hi/lo
__global__ void xsplit_build(const float* __restrict__ x) {
    size_t i4 = (size_t)blockIdx.x * blockDim.x + threadIdx.x;
    float4 v = ((const float4*)x)[i4];
    size_t b = i4 * 4;
    float vv[4] = {v.x, v.y, v.z, v.w};
    #pragma unroll
    for (int p = 0; p < 4; p++) {
        __half hi = __float2half(vv[p]);
        __half lo = __float2half(vv[p] - __half2float(hi));
        g_xh[b + p] = hi;
        g_xl[b + p] = lo;
    }
}

// ---------------------------------------------------------------
// Phase A: gx = x @ Wx^T + b.  fp16 2-combo: (xhi + xlo) . Wfp16.
// Block 128m x 128n x BK64, 256 thr (8 warps = 2m x 4n).
// smem/buffer: [Ahi 18432][Alo 18432][B 18432], 2 buffers = 110592.
// ---------------------------------------------------------------
#define IA_PART  18432
#define IA_BUF   55296
#define IA_DSMEM 110592

__global__ void __launch_bounds__(256) input_hmma(
    const float* __restrict__ bf, const float* __restrict__ bi,
    const float* __restrict__ bo, const float* __restrict__ bc)
{
    extern __shared__ __align__(16) uint8_t dsm[];
    __shared__ float sbias[128];
    const uint32_t sb = smem_u32(dsm);

    const int tid  = threadIdx.x;
    const int lane = tid & 31;
    const int wid  = tid >> 5;
    const int wm   = wid & 1;
    const int wn   = wid >> 1;
    const int gid  = lane >> 2;
    const int tig  = lane & 3;

    const int n0g = blockIdx.x * 128;
    const int m0g = blockIdx.y * 128;

    if (tid < 128) {
        int gate = n0g >> 10;
        const float* bsrc = (gate == 0) ? bf : (gate == 1) ? bi : (gate == 2) ? bo : bc;
        sbias[tid] = bsrc[(n0g & 1023) + tid];
    }

    // fill buffer BUF with k-chunk C (64 k): 12 CP16/thread
    #define IA_FILL(BUF, C) do {                                                 \
        _Pragma("unroll")                                                        \
        for (int i = 0; i < 12; i++) {                                           \
            int e = tid + i * 256;                                               \
            int part = e >> 10, rem = e & 1023;                                  \
            int row = rem >> 3, seg = rem & 7;                                   \
            const __half* src;                                                   \
            if (part == 0)      src = g_xh + (size_t)(m0g + row) * DIN + (C) * 64 + seg * 8; \
            else if (part == 1) src = g_xl + (size_t)(m0g + row) * DIN + (C) * 64 + seg * 8; \
            else                src = g_wx + (size_t)(n0g + row) * DIN + (C) * 64 + seg * 8; \
            CP16(sb + (BUF) * IA_BUF + part * IA_PART + row * 144 + seg * 16, src); \
        }                                                                        \
        CP_COMMIT();                                                             \
    } while (0)

    float acc[4][4][4];
    #pragma unroll
    for (int t = 0; t < 4; t++)
        #pragma unroll
        for (int u = 0; u < 4; u++)
            #pragma unroll
            for (int i = 0; i < 4; i++) acc[t][u][i] = 0.0f;

    IA_FILL(0, 0);
    IA_FILL(1, 1);

    #pragma unroll 1
    for (int c = 0; c < 16; c++) {
        if (c + 2 < 16) CP_WAIT(1); else CP_WAIT(0);
        __syncthreads();
        const uint32_t base = sb + (c & 1) * IA_BUF;

        #pragma unroll
        for (int q = 0; q < 4; q++) {
            const uint32_t kk2 = (uint32_t)(q * 16 + tig * 2) * 2;
            uint32_t aH[4][4], aL[4][4];
            #pragma unroll
            for (int t = 0; t < 4; t++) {
                uint32_t ar = base + (wm * 64 + t * 16 + gid) * 144 + kk2;
                aH[t][0] = lds32(ar);
                aH[t][1] = lds32(ar + 8 * 144);
                aH[t][2] = lds32(ar + 16);
                aH[t][3] = lds32(ar + 8 * 144 + 16);
                aL[t][0] = lds32(ar + IA_PART);
                aL[t][1] = lds32(ar + IA_PART + 8 * 144);
                aL[t][2] = lds32(ar + IA_PART + 16);
                aL[t][3] = lds32(ar + IA_PART + 8 * 144 + 16);
            }
            #pragma unroll
            for (int u = 0; u < 4; u++) {
                uint32_t br = base + 2 * IA_PART + (wn * 32 + u * 8 + gid) * 144 + kk2;
                uint32_t b0 = lds32(br);
                uint32_t b1 = lds32(br + 16);
                #pragma unroll
                for (int t = 0; t < 4; t++) {
                    mma_f16(acc[t][u], aH[t][0], aH[t][1], aH[t][2], aH[t][3], b0, b1);
                    mma_f16(acc[t][u], aL[t][0], aL[t][1], aL[t][2], aL[t][3], b0, b1);
                }
            }
        }
        __syncthreads();
        if (c + 2 < 16) IA_FILL(c & 1, c + 2);
    }

    // epilogue: bias add + v2 stores
    #pragma unroll
    for (int t = 0; t < 4; t++) {
        const int row = m0g + wm * 64 + t * 16 + gid;
        #pragma unroll
        for (int u = 0; u < 4; u++) {
            const int cl = wn * 32 + u * 8 + tig * 2;
            const int col = n0g + cl;
            float b0 = sbias[cl], b1 = sbias[cl + 1];
            float2 v01 = make_float2(acc[t][u][0] + b0, acc[t][u][1] + b1);
            float2 v23 = make_float2(acc[t][u][2] + b0, acc[t][u][3] + b1);
            *(float2*)&g_gx[(size_t)row * NGATE + col]       = v01;
            *(float2*)&g_gx[(size_t)(row + 8) * NGATE + col] = v23;
        }
    }
}

// ---------------------------------------------------------------
// Phase B: PERSISTENT weight-resident HMMA kernel (bf16 3-combo).
// Fast flag/epoch grid barrier, gx prefetched pre-barrier, fast tanh.
// ---------------------------------------------------------------
#define WROW      2064
#define WOFF_SPL  66048
#define BBASE     132096
#define BROW      272
#define BSPL      17408
#define BBUF      34816
#define GXBASE    201728
#define DSMEM_BYTES 210944

__global__ void __launch_bounds__(256) lstm_persistent(float* __restrict__ out)
{
    extern __shared__ __align__(16) uint8_t dsm[];
    const uint32_t sb = smem_u32(dsm);

    const int tid  = threadIdx.x;
    const int lane = tid & 31;
    const int wid  = tid >> 5;
    const int wm   = wid & 1;
    const int wn   = wid >> 1;
    const int n0   = wn * 16;
    const int gid  = lane >> 2;
    const int tig  = lane & 3;

    const int r0 = blockIdx.x * 32;
    const int jb = blockIdx.x * 8;

    // ---- load resident W slice (hi+lo) ----
    #pragma unroll
    for (int i = 0; i < 32; i++) {
        int e = tid + i * 256;
        int s = e >> 12, rem = e & 4095;
        int row = rem >> 7, seg = rem & 127;
        const __nv_bfloat16* src = (s ? g_wlo : g_whi)
            + (size_t)(r0 + row) * DLAT + seg * 8;
        CP16(sb + s * WOFF_SPL + row * WROW + seg * 16, src);
    }
    CP_COMMIT();
    CP_WAIT(0);
    __syncthreads();

    // gx prefetch for step 0
    #define GX_PREF(T) do {                                                      \
        const float* gxt = g_gx + (size_t)(T) * BATCH * NGATE;                   \
        _Pragma("unroll")                                                        \
        for (int i = 0; i < 2; i++) {                                            \
            int e = tid + i * 256;                                               \
            int m = e >> 3, g = (e >> 1) & 3, half = e & 1;                      \
            const float* src = gxt + (size_t)m * NGATE + g * 1024 + jb + half * 4; \
            CP16(sb + GXBASE + m * 144 + g * 32 + half * 16, src);               \
        }                                                                        \
        CP_COMMIT();                                                             \
    } while (0)

    GX_PREF(0);

    float creg[2] = {0.0f, 0.0f};
    const int q0  = tid * 2;
    const int em  = q0 >> 3;
    const int ejl = q0 & 7;

    for (int t = 0; t < SEQ; t++) {
        // ---- fast grid barrier (flags + block0 aggregator + epoch) ----
        if (t > 0) {
            if (tid == 0) st_rel(&g_flags[blockIdx.x], (unsigned)t);
            if (blockIdx.x == 0) {
                if (tid < 128) {
                    while (ld_acq(&g_flags[tid]) < (unsigned)t) {}
                }
                __syncthreads();
                if (tid == 0) st_rel(&g_epoch2, (unsigned)t);
            }
            if (tid == 0) {
                while (ld_acq(&g_epoch2) < (unsigned)t) {}
            }
            __syncthreads();
        }

        const int rb = t & 1;
        const __nv_bfloat16* hhi = g_hhi[rb];
        const __nv_bfloat16* hlo = g_hlo[rb];

        #define FILL_B(C) do {                                                   \
            _Pragma("unroll")                                                    \
            for (int i = 0; i < 8; i++) {                                        \
                int e = tid + i * 256;                                           \
                int s = e >> 10, rem = e & 1023;                                 \
                int row = rem >> 4, seg = rem & 15;                              \
                const __nv_bfloat16* src = (s ? hlo : hhi)                       \
                    + (size_t)row * DLAT + (C) * 128 + seg * 8;                  \
                CP16(sb + BBASE + ((C) & 1) * BBUF + s * BSPL + row * BROW + seg * 16, src); \
            }                                                                    \
            CP_COMMIT();                                                         \
        } while (0)

        FILL_B(0);
        FILL_B(1);

        float aHH[2][4], aHL[2][4], aLH[2][4];
        #pragma unroll
        for (int nt2 = 0; nt2 < 2; nt2++)
            #pragma unroll
            for (int i = 0; i < 4; i++) { aHH[nt2][i] = 0.f; aHL[nt2][i] = 0.f; aLH[nt2][i] = 0.f; }

        #pragma unroll 1
        for (int c = 0; c < 8; c++) {
            if (c + 2 < 8) CP_WAIT(1); else CP_WAIT(0);
            __syncthreads();

            const uint32_t bB = sb + BBASE + (c & 1) * BBUF;
            const int kbase = c * 128;

            #pragma unroll
            for (int q = 0; q < 8; q++) {
                const uint32_t ka = (uint32_t)(q * 16 + tig * 2) * 2;
                const uint32_t ar0 = sb + (wm * 16 + gid) * WROW + (uint32_t)(kbase) * 2 + ka;
                const uint32_t ar1 = ar0 + 8 * WROW;
                uint32_t ah0 = lds32(ar0);
                uint32_t ah1 = lds32(ar1);
                uint32_t ah2 = lds32(ar0 + 16);
                uint32_t ah3 = lds32(ar1 + 16);
                uint32_t al0 = lds32(ar0 + WOFF_SPL);
                uint32_t al1 = lds32(ar1 + WOFF_SPL);
                uint32_t al2 = lds32(ar0 + 16 + WOFF_SPL);
                uint32_t al3 = lds32(ar1 + 16 + WOFF_SPL);
                #pragma unroll
                for (int nt2 = 0; nt2 < 2; nt2++) {
                    const uint32_t br = bB + (n0 + nt2 * 8 + gid) * BROW + ka;
                    uint32_t bh0 = lds32(br);
                    uint32_t bh1 = lds32(br + 16);
                    uint32_t bl0 = lds32(br + BSPL);
                    uint32_t bl1 = lds32(br + BSPL + 16);
                    mma_bf16(aHH[nt2], ah0, ah1, ah2, ah3, bh0, bh1);
                    mma_bf16(aHL[nt2], ah0, ah1, ah2, ah3, bl0, bl1);
                    mma_bf16(aLH[nt2], al0, al1, al2, al3, bh0, bh1);
                }
            }
            __syncthreads();
            if (c + 2 < 8) FILL_B(c + 2);
        }

        // ---- exchange via smem (reuse B buffers) ----
        float* ex = (float*)(dsm + BBASE);
        #pragma unroll
        for (int nt2 = 0; nt2 < 2; nt2++) {
            int R0 = wm * 16 + gid, C0 = n0 + nt2 * 8 + tig * 2;
            ex[R0 * 65 + C0]           = aHH[nt2][0] + aHL[nt2][0] + aLH[nt2][0];
            ex[R0 * 65 + C0 + 1]       = aHH[nt2][1] + aHL[nt2][1] + aLH[nt2][1];
            ex[(R0 + 8) * 65 + C0]     = aHH[nt2][2] + aHL[nt2][2] + aLH[nt2][2];
            ex[(R0 + 8) * 65 + C0 + 1] = aHH[nt2][3] + aHL[nt2][3] + aLH[nt2][3];
        }
        __syncthreads();

        // ---- fused epilogue ----
        const float* gxs = (const float*)(dsm + GXBASE);
        __nv_bfloat16* hwh = g_hhi[rb ^ 1];
        __nv_bfloat16* hwl = g_hlo[rb ^ 1];
        #pragma unroll
        for (int p = 0; p < 2; p++) {
            const int jl = ejl + p;
            const int j  = jb + jl;
            float sf = ex[(jl * 4 + 0) * 65 + em];
            float si = ex[(jl * 4 + 1) * 65 + em];
            float so = ex[(jl * 4 + 2) * 65 + em];
            float sg = ex[(jl * 4 + 3) * 65 + em];
            float vf = sigmoidf_(sf + gxs[em * 36 + 0 * 8 + jl]);
            float vi = sigmoidf_(si + gxs[em * 36 + 1 * 8 + jl]);
            float vo = sigmoidf_(so + gxs[em * 36 + 2 * 8 + jl]);
            float vg = tanhf_(sg + gxs[em * 36 + 3 * 8 + jl]);
            float cc = vf * creg[p] + vi * vg;
            creg[p] = cc;
            float h = vo * tanhf_(cc);
            out[((size_t)t * BATCH + em) * DLAT + j] = h;
            __nv_bfloat16 hh = __float2bfloat16(h);
            __nv_bfloat16 hl = __float2bfloat16(h - __bfloat162float(hh));
            hwh[(size_t)em * DLAT + j] = hh;
            hwl[(size_t)em * DLAT + j] = hl;
        }
        __syncthreads();
        if (t + 1 < SEQ) GX_PREF(t + 1);   // gx is barrier-independent
    }
}

// ---------------------------------------------------------------
extern "C" void kernel_launch(void* const* d_in, const int* in_sizes, int n_in,
                              void* d_out, int out_size)
{
    const float* x  = (const float*)d_in[0];
    const float* Wf = (const float*)d_in[1];
    const float* bf = (const float*)d_in[2];
    const float* Wi = (const float*)d_in[3];
    const float* bi = (const float*)d_in[4];
    const float* Wo = (const float*)d_in[5];
    const float* bo = (const float*)d_in[6];
    const float* Wc = (const float*)d_in[7];
    const float* bc = (const float*)d_in[8];
    float* out = (float*)d_out;

    cudaFuncSetAttribute(input_hmma, cudaFuncAttributeMaxDynamicSharedMemorySize,
                         IA_DSMEM);
    cudaFuncSetAttribute(lstm_persistent, cudaFuncAttributeMaxDynamicSharedMemorySize,
                         DSMEM_BYTES);

    init_state<<<256, 256>>>();
    wsplit_build<<<(NGATE * DCAT) / 256, 256>>>(Wf, Wi, Wo, Wc);
    xsplit_build<<<(SEQ * BATCH * DIN) / (4 * 256), 256>>>(x);

    dim3 gridA(NGATE / 128, (SEQ * BATCH) / 128);   // (32, 256)
    input_hmma<<<gridA, 256, IA_DSMEM>>>(bf, bi, bo, bc);

    lstm_persistent<<<128, 256, DSMEM_BYTES>>>(out);
}